// round 9
// baseline (speedup 1.0000x reference)
#include <cuda_runtime.h>
#include <cuda_bf16.h>

#define D_DIM   512
#define H1_DIM  128
#define H2_DIM  64
#define B_DIM   2048
#define N_NODES 20000
#define N_DRUG  2000

typedef unsigned long long ull;

__device__ __forceinline__ unsigned smem_u32(const void* p) {
    unsigned a;
    asm("{ .reg .u64 t; cvta.to.shared.u64 t, %1; cvt.u32.u64 %0, t; }" : "=r"(a) : "l"(p));
    return a;
}

#define SW128(o) ((o) ^ ((((o) >> 3) & 0x70)))

// Scratch
__device__ float g_Ptop[N_DRUG  * H1_DIM];       // embed[:2000]  @ W1[0:512]
__device__ float g_Pbot[N_NODES * H1_DIM];       // embed[:20000] @ W1[512:1024]
__device__ __nv_bfloat16 g_Wthi[H1_DIM * 1024];  // W1^T hi  [n][k]
__device__ __nv_bfloat16 g_Wtlo[H1_DIM * 1024];  // W1^T lo  [n][k]
__device__ __nv_bfloat16 g_W2thi[H2_DIM * H1_DIM]; // W2^T hi [n][k]
__device__ __nv_bfloat16 g_W2tlo[H2_DIM * H1_DIM]; // W2^T lo [n][k]

// ---------------------------------------------------------------------------
// Kernel 0a: W1 (fp32 [1024][128]) -> bf16 hi/lo [128][1024], coalesced both ways
// Grid 32 blocks: block b handles k rows [32b, 32b+32).
// ---------------------------------------------------------------------------
__global__ void __launch_bounds__(256) convert_w1_kernel(const float* __restrict__ W1) {
    __shared__ unsigned short s_hi[128][34];
    __shared__ unsigned short s_lo[128][34];
    const int tid = threadIdx.x;
    const int k0 = blockIdx.x * 32;
#pragma unroll
    for (int it = 0; it < 16; it++) {
        int idx = it * 256 + tid;
        int kk = idx >> 7;          // 0..31
        int n  = idx & 127;
        float x = W1[(k0 + kk) * H1_DIM + n];
        __nv_bfloat16 hb = __float2bfloat16(x);
        float hf = __bfloat162float(hb);
        __nv_bfloat16 lb = __float2bfloat16(x - hf);
        s_hi[n][kk] = __bfloat16_as_ushort(hb);
        s_lo[n][kk] = __bfloat16_as_ushort(lb);
    }
    __syncthreads();
#pragma unroll
    for (int it = 0; it < 16; it++) {
        int idx = it * 256 + tid;
        int n  = idx >> 5;          // 0..127
        int kk = idx & 31;
        g_Wthi[n * 1024 + k0 + kk] = __ushort_as_bfloat16(s_hi[n][kk]);
        g_Wtlo[n * 1024 + k0 + kk] = __ushort_as_bfloat16(s_lo[n][kk]);
    }
}

// ---------------------------------------------------------------------------
// Kernel 0b: W2 (fp32 [128][64]) -> bf16 hi/lo [64][128] (tiny)
// ---------------------------------------------------------------------------
__global__ void __launch_bounds__(256) convert_w2_kernel(const float* __restrict__ W2) {
    const int tid = threadIdx.x;
    const int n  = tid >> 2;          // 0..63
    const int kr = (tid & 3) * 32;    // k run base
#pragma unroll
    for (int kk = 0; kk < 32; kk++) {
        float x = W2[(kr + kk) * H2_DIM + n];
        __nv_bfloat16 hb = __float2bfloat16(x);
        float hf = __bfloat162float(hb);
        g_W2thi[n * H1_DIM + kr + kk] = hb;
        g_W2tlo[n * H1_DIM + kr + kk] = __float2bfloat16(x - hf);
    }
}

// ---------------------------------------------------------------------------
// Shared HMMA helpers (validated in R8)
// ---------------------------------------------------------------------------
__device__ __forceinline__ void ldm_x4(unsigned addr, unsigned& r0, unsigned& r1,
                                       unsigned& r2, unsigned& r3) {
    asm volatile("ldmatrix.sync.aligned.m8n8.x4.shared.b16 {%0,%1,%2,%3}, [%4];"
                 : "=r"(r0), "=r"(r1), "=r"(r2), "=r"(r3) : "r"(addr));
}
__device__ __forceinline__ void mma_bf16(float* c, unsigned a0, unsigned a1,
                                         unsigned a2, unsigned a3,
                                         unsigned b0, unsigned b1) {
    asm volatile("mma.sync.aligned.m16n8k16.row.col.f32.bf16.bf16.f32 "
                 "{%0,%1,%2,%3}, {%4,%5,%6,%7}, {%8,%9}, {%0,%1,%2,%3};"
                 : "+f"(c[0]), "+f"(c[1]), "+f"(c[2]), "+f"(c[3])
                 : "r"(a0), "r"(a1), "r"(a2), "r"(a3), "r"(b0), "r"(b1));
}
__device__ __forceinline__ unsigned amat_addr(unsigned base, int m0, int k0, int lane) {
    unsigned off = (unsigned)((m0 + (lane & 15)) * 128 + ((k0 >> 3) + (lane >> 4)) * 16);
    return base + SW128(off);
}
__device__ __forceinline__ unsigned bmat_addr(unsigned base, int n0, int k0, int lane) {
    unsigned off = (unsigned)((n0 + (lane & 7) + ((lane >> 4) << 3)) * 128
                            + ((k0 >> 3) + ((lane >> 3) & 1)) * 16);
    return base + SW128(off);
}
__device__ __forceinline__ void split4(float4 v, unsigned& hi01, unsigned& hi23,
                                       unsigned& lo01, unsigned& lo23) {
    asm("cvt.rn.bf16x2.f32 %0, %1, %2;" : "=r"(hi01) : "f"(v.y), "f"(v.x));
    asm("cvt.rn.bf16x2.f32 %0, %1, %2;" : "=r"(hi23) : "f"(v.w), "f"(v.z));
    float h0 = __uint_as_float(hi01 << 16);
    float h1 = __uint_as_float(hi01 & 0xffff0000u);
    float h2 = __uint_as_float(hi23 << 16);
    float h3 = __uint_as_float(hi23 & 0xffff0000u);
    asm("cvt.rn.bf16x2.f32 %0, %1, %2;" : "=r"(lo01) : "f"(v.y - h1), "f"(v.x - h0));
    asm("cvt.rn.bf16x2.f32 %0, %1, %2;" : "=r"(lo23) : "f"(v.w - h3), "f"(v.z - h2));
}

// ---------------------------------------------------------------------------
// Kernel 1: gemm1 HMMA (unchanged from R8, validated)
// ---------------------------------------------------------------------------
#define NBOT_TC 157
#define NTOP_TC 16

#define SM_AHI 0
#define SM_ALO 16384
#define SM_BHI 32768
#define SM_BLO 49152
#define G1_SMEM 65536

__global__ void __launch_bounds__(256) gemm1_mma_kernel(const float* __restrict__ embed) {
    extern __shared__ char sm[];
    const unsigned sb = smem_u32(sm);
    const int tid = threadIdx.x;
    const int wid = tid >> 5;
    const int lane = tid & 31;

    int bx = blockIdx.x;
    int woff, M, row0;
    float* P;
    if (bx < NBOT_TC) { woff = D_DIM; M = N_NODES; P = g_Pbot; row0 = bx * 128; }
    else { bx -= NBOT_TC; woff = 0; M = N_DRUG; P = g_Ptop; row0 = bx * 128; }
    const int rmax = M - 1;

    const int wr = wid >> 2;
    const int wc = wid & 3;
    const int nb = wc * 32;

    float acc[4][4][4];
#pragma unroll
    for (int i = 0; i < 4; i++)
#pragma unroll
        for (int j = 0; j < 4; j++)
#pragma unroll
            for (int q = 0; q < 4; q++) acc[i][j][q] = 0.f;

    const int kq = tid & 15;
    const int rr = tid >> 4;

    for (int c = 0; c < 8; c++) {
        const int kb = c * 64;
#pragma unroll
        for (int p = 0; p < 8; p++) {
            int row = p * 16 + rr;
            int rg = min(row0 + row, rmax);
            float4 v = *(const float4*)&embed[(size_t)rg * D_DIM + kb + kq * 4];
            unsigned hi01, hi23, lo01, lo23;
            split4(v, hi01, hi23, lo01, lo23);
            unsigned off = SW128((unsigned)(row * 128 + kq * 8));
            *(uint2*)(sm + SM_AHI + off) = make_uint2(hi01, hi23);
            *(uint2*)(sm + SM_ALO + off) = make_uint2(lo01, lo23);
            *(uint2*)(sm + SM_BHI + off) = *(const uint2*)&g_Wthi[row * 1024 + woff + kb + kq * 4];
            *(uint2*)(sm + SM_BLO + off) = *(const uint2*)&g_Wtlo[row * 1024 + woff + kb + kq * 4];
        }
        __syncthreads();

#pragma unroll
        for (int ks = 0; ks < 4; ks++) {
            const int k0 = ks * 16;
            unsigned bh[4][2], bl[4][2], t0, t1, t2, t3;
            ldm_x4(bmat_addr(sb + SM_BHI, nb,      k0, lane), t0, t1, t2, t3);
            bh[0][0] = t0; bh[0][1] = t1; bh[1][0] = t2; bh[1][1] = t3;
            ldm_x4(bmat_addr(sb + SM_BHI, nb + 16, k0, lane), t0, t1, t2, t3);
            bh[2][0] = t0; bh[2][1] = t1; bh[3][0] = t2; bh[3][1] = t3;
            ldm_x4(bmat_addr(sb + SM_BLO, nb,      k0, lane), t0, t1, t2, t3);
            bl[0][0] = t0; bl[0][1] = t1; bl[1][0] = t2; bl[1][1] = t3;
            ldm_x4(bmat_addr(sb + SM_BLO, nb + 16, k0, lane), t0, t1, t2, t3);
            bl[2][0] = t0; bl[2][1] = t1; bl[3][0] = t2; bl[3][1] = t3;
#pragma unroll
            for (int mf = 0; mf < 4; mf++) {
                const int m0 = wr * 64 + mf * 16;
                unsigned ah0, ah1, ah2, ah3, al0, al1, al2, al3;
                ldm_x4(amat_addr(sb + SM_AHI, m0, k0, lane), ah0, ah1, ah2, ah3);
                ldm_x4(amat_addr(sb + SM_ALO, m0, k0, lane), al0, al1, al2, al3);
#pragma unroll
                for (int nf = 0; nf < 4; nf++) {
                    mma_bf16(acc[mf][nf], ah0, ah1, ah2, ah3, bh[nf][0], bh[nf][1]);
                    mma_bf16(acc[mf][nf], ah0, ah1, ah2, ah3, bl[nf][0], bl[nf][1]);
                    mma_bf16(acc[mf][nf], al0, al1, al2, al3, bh[nf][0], bh[nf][1]);
                }
            }
        }
        __syncthreads();
    }

#pragma unroll
    for (int mf = 0; mf < 4; mf++) {
#pragma unroll
        for (int nf = 0; nf < 4; nf++) {
            int r = row0 + wr * 64 + mf * 16 + (lane >> 2);
            int col = nb + nf * 8 + 2 * (lane & 3);
            if (r < M)
                *(float2*)&P[(size_t)r * H1_DIM + col] =
                    make_float2(acc[mf][nf][0], acc[mf][nf][1]);
            if (r + 8 < M)
                *(float2*)&P[(size_t)(r + 8) * H1_DIM + col] =
                    make_float2(acc[mf][nf][2], acc[mf][nf][3]);
        }
    }
}

// ---------------------------------------------------------------------------
// Kernel 2: mlp2 HMMA. 128 samples/block, 256 threads (8 warps of 32m x 32n).
// X1 split-built into bf16 hi/lo SW128 tiles (2 k-chunks of 64), W2 pre-split.
// Layer 3 via shfl + smem cross-warp reduction.
// ---------------------------------------------------------------------------
#define M2_XHI 0
#define M2_XLO 16384
#define M2_WHI 32768
#define M2_WLO 40960
#define M2_MISC 49152
// misc floats: b1s[128], b2s[64], W3s[64], partial[256]; ints sTop/sBot/sOut[128]
#define M2_SMEM (M2_MISC + (128 + 64 + 64 + 256 + 3 * 128) * 4)

__global__ void __launch_bounds__(256) mlp2_mma_kernel(
    const int* __restrict__ h, const int* __restrict__ t, const int* __restrict__ ns,
    const float* __restrict__ b1, const float* __restrict__ b2,
    const float* __restrict__ W3, const float* __restrict__ b3,
    float* __restrict__ out)
{
    extern __shared__ char sm[];
    const unsigned sb = smem_u32(sm);
    float* b1s   = (float*)(sm + M2_MISC);
    float* b2s   = b1s + 128;
    float* W3s   = b2s + 64;
    float* partial = W3s + 64;                 // [128][2]
    int* sTop = (int*)(partial + 256);
    int* sBot = sTop + 128;
    int* sOut = sBot + 128;

    const int tid = threadIdx.x;
    const int wid = tid >> 5;
    const int lane = tid & 31;

    // ---- phase 0 ----
    if (tid < 128) {
        int S = blockIdx.x * 128 + tid;
        int b = S / 65;
        int r = S - b * 65;
        int itop, jbot, oaddr;
        if (r == 64)      { itop = h[b];           jbot = t[b];           oaddr = b; }
        else if (r < 32)  { itop = h[b];           jbot = ns[b * 64 + r]; oaddr = B_DIM + b * 64 + r; }
        else              { itop = ns[b * 64 + r]; jbot = t[b];           oaddr = B_DIM + b * 64 + r; }
        sTop[tid] = itop; sBot[tid] = jbot; sOut[tid] = oaddr;
        b1s[tid] = b1[tid];
    }
    if (tid < 64) { b2s[tid] = b2[tid]; W3s[tid] = W3[tid]; }
    __syncthreads();

    const int wm = wid >> 1;        // 0..3 -> m0 = 32*wm
    const int wn = wid & 1;         // 0..1 -> nb = 32*wn
    const int nb = wn * 32;

    float acc[2][4][4];
#pragma unroll
    for (int i = 0; i < 2; i++)
#pragma unroll
        for (int j = 0; j < 4; j++)
#pragma unroll
            for (int q = 0; q < 4; q++) acc[i][j][q] = 0.f;

    const int s1 = tid >> 1;            // sample for phase-1 staging
    const int kh = (tid & 1) * 32;      // k half within chunk

#pragma unroll
    for (int c = 0; c < 2; c++) {
        const int koff = c * 64;
        // ---- stage X1 hi/lo: x = relu(Ptop[i][k]+Pbot[j][k]+b1[k]) ----
        {
            const float* pt = g_Ptop + (size_t)sTop[s1] * H1_DIM + koff + kh;
            const float* pb = g_Pbot + (size_t)sBot[s1] * H1_DIM + koff + kh;
            const float* bb = b1s + koff + kh;
#pragma unroll
            for (int g = 0; g < 8; g++) {
                float4 pa = *(const float4*)&pt[g * 4];
                float4 pv = *(const float4*)&pb[g * 4];
                float4 vb = *(const float4*)&bb[g * 4];
                float4 x;
                x.x = fmaxf(pa.x + pv.x + vb.x, 0.f);
                x.y = fmaxf(pa.y + pv.y + vb.y, 0.f);
                x.z = fmaxf(pa.z + pv.z + vb.z, 0.f);
                x.w = fmaxf(pa.w + pv.w + vb.w, 0.f);
                unsigned hi01, hi23, lo01, lo23;
                split4(x, hi01, hi23, lo01, lo23);
                unsigned off = SW128((unsigned)(s1 * 128 + (kh + g * 4) * 2));
                *(uint2*)(sm + M2_XHI + off) = make_uint2(hi01, hi23);
                *(uint2*)(sm + M2_XLO + off) = make_uint2(lo01, lo23);
            }
        }
        // ---- stage W2 tile [64 n][64 k] hi/lo ----
#pragma unroll
        for (int it = 0; it < 4; it++) {
            int idx = it * 256 + tid;        // 0..1023 uint2 groups
            int n = idx >> 4;
            int kq = idx & 15;
            unsigned off = SW128((unsigned)(n * 128 + kq * 8));
            *(uint2*)(sm + M2_WHI + off) = *(const uint2*)&g_W2thi[n * H1_DIM + koff + kq * 4];
            *(uint2*)(sm + M2_WLO + off) = *(const uint2*)&g_W2tlo[n * H1_DIM + koff + kq * 4];
        }
        __syncthreads();

        // ---- compute 4 k16 steps ----
#pragma unroll
        for (int ks = 0; ks < 4; ks++) {
            const int k0 = ks * 16;
            unsigned bh[4][2], bl[4][2], t0, t1, t2, t3;
            ldm_x4(bmat_addr(sb + M2_WHI, nb,      k0, lane), t0, t1, t2, t3);
            bh[0][0] = t0; bh[0][1] = t1; bh[1][0] = t2; bh[1][1] = t3;
            ldm_x4(bmat_addr(sb + M2_WHI, nb + 16, k0, lane), t0, t1, t2, t3);
            bh[2][0] = t0; bh[2][1] = t1; bh[3][0] = t2; bh[3][1] = t3;
            ldm_x4(bmat_addr(sb + M2_WLO, nb,      k0, lane), t0, t1, t2, t3);
            bl[0][0] = t0; bl[0][1] = t1; bl[1][0] = t2; bl[1][1] = t3;
            ldm_x4(bmat_addr(sb + M2_WLO, nb + 16, k0, lane), t0, t1, t2, t3);
            bl[2][0] = t0; bl[2][1] = t1; bl[3][0] = t2; bl[3][1] = t3;
#pragma unroll
            for (int mf = 0; mf < 2; mf++) {
                const int m0 = wm * 32 + mf * 16;
                unsigned ah0, ah1, ah2, ah3, al0, al1, al2, al3;
                ldm_x4(amat_addr(sb + M2_XHI, m0, k0, lane), ah0, ah1, ah2, ah3);
                ldm_x4(amat_addr(sb + M2_XLO, m0, k0, lane), al0, al1, al2, al3);
#pragma unroll
                for (int nf = 0; nf < 4; nf++) {
                    mma_bf16(acc[mf][nf], ah0, ah1, ah2, ah3, bh[nf][0], bh[nf][1]);
                    mma_bf16(acc[mf][nf], ah0, ah1, ah2, ah3, bl[nf][0], bl[nf][1]);
                    mma_bf16(acc[mf][nf], al0, al1, al2, al3, bh[nf][0], bh[nf][1]);
                }
            }
        }
        __syncthreads();
    }

    // ---- layer 3: relu(acc + b2) . W3, reduce ----
#pragma unroll
    for (int mf = 0; mf < 2; mf++) {
        float p0 = 0.f, p8 = 0.f;
#pragma unroll
        for (int nf = 0; nf < 4; nf++) {
            int n0 = nb + nf * 8 + 2 * (lane & 3);
            float b20 = b2s[n0], b21 = b2s[n0 + 1];
            float w30 = W3s[n0], w31 = W3s[n0 + 1];
            p0 = fmaf(fmaxf(acc[mf][nf][0] + b20, 0.f), w30, p0);
            p0 = fmaf(fmaxf(acc[mf][nf][1] + b21, 0.f), w31, p0);
            p8 = fmaf(fmaxf(acc[mf][nf][2] + b20, 0.f), w30, p8);
            p8 = fmaf(fmaxf(acc[mf][nf][3] + b21, 0.f), w31, p8);
        }
        p0 += __shfl_xor_sync(0xffffffffu, p0, 1);
        p0 += __shfl_xor_sync(0xffffffffu, p0, 2);
        p8 += __shfl_xor_sync(0xffffffffu, p8, 1);
        p8 += __shfl_xor_sync(0xffffffffu, p8, 2);
        if ((lane & 3) == 0) {
            int r = wm * 32 + mf * 16 + (lane >> 2);
            partial[r * 2 + wn]       = p0;
            partial[(r + 8) * 2 + wn] = p8;
        }
    }
    __syncthreads();
    if (tid < 128)
        out[sOut[tid]] = partial[tid * 2] + partial[tid * 2 + 1] + b3[0];
}

// ---------------------------------------------------------------------------
extern "C" void kernel_launch(void* const* d_in, const int* in_sizes, int n_in,
                              void* d_out, int out_size) {
    const float* embed = (const float*)d_in[0];
    const float* W1    = (const float*)d_in[1];
    const float* b1    = (const float*)d_in[2];
    const float* W2    = (const float*)d_in[3];
    const float* b2    = (const float*)d_in[4];
    const float* W3    = (const float*)d_in[5];
    const float* b3    = (const float*)d_in[6];
    const int*   h     = (const int*)d_in[7];
    const int*   t     = (const int*)d_in[8];
    const int*   ns    = (const int*)d_in[9];
    float* out = (float*)d_out;

    convert_w1_kernel<<<32, 256>>>(W1);
    convert_w2_kernel<<<1, 256>>>(W2);

    cudaFuncSetAttribute(gemm1_mma_kernel, cudaFuncAttributeMaxDynamicSharedMemorySize,
                         G1_SMEM);
    gemm1_mma_kernel<<<NBOT_TC + NTOP_TC, 256, G1_SMEM>>>(embed);

    cudaFuncSetAttribute(mlp2_mma_kernel, cudaFuncAttributeMaxDynamicSharedMemorySize,
                         M2_SMEM);
    mlp2_mma_kernel<<<(B_DIM * 65) / 128, 256, M2_SMEM>>>(h, t, ns, b1, b2, W3, b3, out);
}

// round 10
// speedup vs baseline: 1.1082x; 1.1082x over previous
#include <cuda_runtime.h>
#include <cuda_bf16.h>

#define D_DIM   512
#define H1_DIM  128
#define H2_DIM  64
#define B_DIM   2048
#define N_NODES 20000
#define N_DRUG  2000

typedef unsigned long long ull;

__device__ __forceinline__ unsigned smem_u32(const void* p) {
    unsigned a;
    asm("{ .reg .u64 t; cvta.to.shared.u64 t, %1; cvt.u32.u64 %0, t; }" : "=r"(a) : "l"(p));
    return a;
}

#define SW128(o) ((o) ^ ((((o) >> 3) & 0x70)))

// Scratch
__device__ float g_Ptop[N_DRUG  * H1_DIM];       // embed[:2000]  @ W1[0:512]
__device__ float g_Pbot[N_NODES * H1_DIM];       // embed[:20000] @ W1[512:1024]
__device__ __nv_bfloat16 g_Wthi[H1_DIM * 1024];  // W1^T hi  [n][k]
__device__ __nv_bfloat16 g_Wtlo[H1_DIM * 1024];  // W1^T lo  [n][k]
__device__ __nv_bfloat16 g_W2thi[H2_DIM * H1_DIM]; // W2^T hi [n][k]
__device__ __nv_bfloat16 g_W2tlo[H2_DIM * H1_DIM]; // W2^T lo [n][k]

// ---------------------------------------------------------------------------
// Kernel 0a: W1 (fp32 [1024][128]) -> bf16 hi/lo [128][1024], coalesced
// ---------------------------------------------------------------------------
__global__ void __launch_bounds__(256) convert_w1_kernel(const float* __restrict__ W1) {
    __shared__ unsigned short s_hi[128][34];
    __shared__ unsigned short s_lo[128][34];
    const int tid = threadIdx.x;
    const int k0 = blockIdx.x * 32;
#pragma unroll
    for (int it = 0; it < 16; it++) {
        int idx = it * 256 + tid;
        int kk = idx >> 7;          // 0..31
        int n  = idx & 127;
        float x = W1[(k0 + kk) * H1_DIM + n];
        __nv_bfloat16 hb = __float2bfloat16(x);
        float hf = __bfloat162float(hb);
        __nv_bfloat16 lb = __float2bfloat16(x - hf);
        s_hi[n][kk] = __bfloat16_as_ushort(hb);
        s_lo[n][kk] = __bfloat16_as_ushort(lb);
    }
    __syncthreads();
#pragma unroll
    for (int it = 0; it < 16; it++) {
        int idx = it * 256 + tid;
        int n  = idx >> 5;          // 0..127
        int kk = idx & 31;
        g_Wthi[n * 1024 + k0 + kk] = __ushort_as_bfloat16(s_hi[n][kk]);
        g_Wtlo[n * 1024 + k0 + kk] = __ushort_as_bfloat16(s_lo[n][kk]);
    }
}

// ---------------------------------------------------------------------------
// Kernel 0b: W2 (fp32 [128][64]) -> bf16 hi/lo [64][128]
// 32 blocks x 256 threads, one element per thread (was: 1 block, 15+us!)
// ---------------------------------------------------------------------------
__global__ void __launch_bounds__(256) convert_w2_kernel(const float* __restrict__ W2) {
    int idx = blockIdx.x * 256 + threadIdx.x;   // 0..8191
    int k = idx >> 6;         // 0..127
    int n = idx & 63;         // coalesced read within warp
    float x = W2[k * H2_DIM + n];
    __nv_bfloat16 hb = __float2bfloat16(x);
    float hf = __bfloat162float(hb);
    g_W2thi[n * H1_DIM + k] = hb;
    g_W2tlo[n * H1_DIM + k] = __float2bfloat16(x - hf);
}

// ---------------------------------------------------------------------------
// Shared HMMA helpers (validated)
// ---------------------------------------------------------------------------
__device__ __forceinline__ void ldm_x4(unsigned addr, unsigned& r0, unsigned& r1,
                                       unsigned& r2, unsigned& r3) {
    asm volatile("ldmatrix.sync.aligned.m8n8.x4.shared.b16 {%0,%1,%2,%3}, [%4];"
                 : "=r"(r0), "=r"(r1), "=r"(r2), "=r"(r3) : "r"(addr));
}
__device__ __forceinline__ void mma_bf16(float* c, unsigned a0, unsigned a1,
                                         unsigned a2, unsigned a3,
                                         unsigned b0, unsigned b1) {
    asm volatile("mma.sync.aligned.m16n8k16.row.col.f32.bf16.bf16.f32 "
                 "{%0,%1,%2,%3}, {%4,%5,%6,%7}, {%8,%9}, {%0,%1,%2,%3};"
                 : "+f"(c[0]), "+f"(c[1]), "+f"(c[2]), "+f"(c[3])
                 : "r"(a0), "r"(a1), "r"(a2), "r"(a3), "r"(b0), "r"(b1));
}
__device__ __forceinline__ unsigned amat_addr(unsigned base, int m0, int k0, int lane) {
    unsigned off = (unsigned)((m0 + (lane & 15)) * 128 + ((k0 >> 3) + (lane >> 4)) * 16);
    return base + SW128(off);
}
__device__ __forceinline__ unsigned bmat_addr(unsigned base, int n0, int k0, int lane) {
    unsigned off = (unsigned)((n0 + (lane & 7) + ((lane >> 4) << 3)) * 128
                            + ((k0 >> 3) + ((lane >> 3) & 1)) * 16);
    return base + SW128(off);
}
__device__ __forceinline__ void split4(float4 v, unsigned& hi01, unsigned& hi23,
                                       unsigned& lo01, unsigned& lo23) {
    asm("cvt.rn.bf16x2.f32 %0, %1, %2;" : "=r"(hi01) : "f"(v.y), "f"(v.x));
    asm("cvt.rn.bf16x2.f32 %0, %1, %2;" : "=r"(hi23) : "f"(v.w), "f"(v.z));
    float h0 = __uint_as_float(hi01 << 16);
    float h1 = __uint_as_float(hi01 & 0xffff0000u);
    float h2 = __uint_as_float(hi23 << 16);
    float h3 = __uint_as_float(hi23 & 0xffff0000u);
    asm("cvt.rn.bf16x2.f32 %0, %1, %2;" : "=r"(lo01) : "f"(v.y - h1), "f"(v.x - h0));
    asm("cvt.rn.bf16x2.f32 %0, %1, %2;" : "=r"(lo23) : "f"(v.w - h3), "f"(v.z - h2));
}

// ---------------------------------------------------------------------------
// Kernel 1: gemm1 HMMA (unchanged from R8, validated)
// ---------------------------------------------------------------------------
#define NBOT_TC 157
#define NTOP_TC 16

#define SM_AHI 0
#define SM_ALO 16384
#define SM_BHI 32768
#define SM_BLO 49152
#define G1_SMEM 65536

__global__ void __launch_bounds__(256) gemm1_mma_kernel(const float* __restrict__ embed) {
    extern __shared__ char sm[];
    const unsigned sb = smem_u32(sm);
    const int tid = threadIdx.x;
    const int wid = tid >> 5;
    const int lane = tid & 31;

    int bx = blockIdx.x;
    int woff, M, row0;
    float* P;
    if (bx < NBOT_TC) { woff = D_DIM; M = N_NODES; P = g_Pbot; row0 = bx * 128; }
    else { bx -= NBOT_TC; woff = 0; M = N_DRUG; P = g_Ptop; row0 = bx * 128; }
    const int rmax = M - 1;

    const int wr = wid >> 2;
    const int wc = wid & 3;
    const int nb = wc * 32;

    float acc[4][4][4];
#pragma unroll
    for (int i = 0; i < 4; i++)
#pragma unroll
        for (int j = 0; j < 4; j++)
#pragma unroll
            for (int q = 0; q < 4; q++) acc[i][j][q] = 0.f;

    const int kq = tid & 15;
    const int rr = tid >> 4;

    for (int c = 0; c < 8; c++) {
        const int kb = c * 64;
#pragma unroll
        for (int p = 0; p < 8; p++) {
            int row = p * 16 + rr;
            int rg = min(row0 + row, rmax);
            float4 v = *(const float4*)&embed[(size_t)rg * D_DIM + kb + kq * 4];
            unsigned hi01, hi23, lo01, lo23;
            split4(v, hi01, hi23, lo01, lo23);
            unsigned off = SW128((unsigned)(row * 128 + kq * 8));
            *(uint2*)(sm + SM_AHI + off) = make_uint2(hi01, hi23);
            *(uint2*)(sm + SM_ALO + off) = make_uint2(lo01, lo23);
            *(uint2*)(sm + SM_BHI + off) = *(const uint2*)&g_Wthi[row * 1024 + woff + kb + kq * 4];
            *(uint2*)(sm + SM_BLO + off) = *(const uint2*)&g_Wtlo[row * 1024 + woff + kb + kq * 4];
        }
        __syncthreads();

#pragma unroll
        for (int ks = 0; ks < 4; ks++) {
            const int k0 = ks * 16;
            unsigned bh[4][2], bl[4][2], t0, t1, t2, t3;
            ldm_x4(bmat_addr(sb + SM_BHI, nb,      k0, lane), t0, t1, t2, t3);
            bh[0][0] = t0; bh[0][1] = t1; bh[1][0] = t2; bh[1][1] = t3;
            ldm_x4(bmat_addr(sb + SM_BHI, nb + 16, k0, lane), t0, t1, t2, t3);
            bh[2][0] = t0; bh[2][1] = t1; bh[3][0] = t2; bh[3][1] = t3;
            ldm_x4(bmat_addr(sb + SM_BLO, nb,      k0, lane), t0, t1, t2, t3);
            bl[0][0] = t0; bl[0][1] = t1; bl[1][0] = t2; bl[1][1] = t3;
            ldm_x4(bmat_addr(sb + SM_BLO, nb + 16, k0, lane), t0, t1, t2, t3);
            bl[2][0] = t0; bl[2][1] = t1; bl[3][0] = t2; bl[3][1] = t3;
#pragma unroll
            for (int mf = 0; mf < 4; mf++) {
                const int m0 = wr * 64 + mf * 16;
                unsigned ah0, ah1, ah2, ah3, al0, al1, al2, al3;
                ldm_x4(amat_addr(sb + SM_AHI, m0, k0, lane), ah0, ah1, ah2, ah3);
                ldm_x4(amat_addr(sb + SM_ALO, m0, k0, lane), al0, al1, al2, al3);
#pragma unroll
                for (int nf = 0; nf < 4; nf++) {
                    mma_bf16(acc[mf][nf], ah0, ah1, ah2, ah3, bh[nf][0], bh[nf][1]);
                    mma_bf16(acc[mf][nf], ah0, ah1, ah2, ah3, bl[nf][0], bl[nf][1]);
                    mma_bf16(acc[mf][nf], al0, al1, al2, al3, bh[nf][0], bh[nf][1]);
                }
            }
        }
        __syncthreads();
    }

#pragma unroll
    for (int mf = 0; mf < 4; mf++) {
#pragma unroll
        for (int nf = 0; nf < 4; nf++) {
            int r = row0 + wr * 64 + mf * 16 + (lane >> 2);
            int col = nb + nf * 8 + 2 * (lane & 3);
            if (r < M)
                *(float2*)&P[(size_t)r * H1_DIM + col] =
                    make_float2(acc[mf][nf][0], acc[mf][nf][1]);
            if (r + 8 < M)
                *(float2*)&P[(size_t)(r + 8) * H1_DIM + col] =
                    make_float2(acc[mf][nf][2], acc[mf][nf][3]);
        }
    }
}

// ---------------------------------------------------------------------------
// Kernel 2 v2: stage EVERYTHING (both 64-k chunks of X1 hi/lo + W2 hi/lo),
// one barrier, then 384 uninterrupted HMMA per warp.
// smem: X 64KB + W2 32KB + misc ~3.5KB.
// ---------------------------------------------------------------------------
#define M2_XHI 0                  // 2 chunks x 16KB
#define M2_XLO 32768              // 2 chunks x 16KB
#define M2_WHI 65536              // 2 chunks x 8KB
#define M2_WLO 81920              // 2 chunks x 8KB
#define M2_MISC 98304
#define M2_SMEM (M2_MISC + (128 + 64 + 64 + 256 + 3 * 128) * 4)

__global__ void __launch_bounds__(256) mlp2_mma_kernel(
    const int* __restrict__ h, const int* __restrict__ t, const int* __restrict__ ns,
    const float* __restrict__ b1, const float* __restrict__ b2,
    const float* __restrict__ W3, const float* __restrict__ b3,
    float* __restrict__ out)
{
    extern __shared__ char sm[];
    const unsigned sb = smem_u32(sm);
    float* b1s   = (float*)(sm + M2_MISC);
    float* b2s   = b1s + 128;
    float* W3s   = b2s + 64;
    float* partial = W3s + 64;                 // [128][2]
    int* sTop = (int*)(partial + 256);
    int* sBot = sTop + 128;
    int* sOut = sBot + 128;

    const int tid = threadIdx.x;
    const int wid = tid >> 5;
    const int lane = tid & 31;

    // ---- phase 0: indices + small tensors ----
    if (tid < 128) {
        int S = blockIdx.x * 128 + tid;
        int b = S / 65;
        int r = S - b * 65;
        int itop, jbot, oaddr;
        if (r == 64)      { itop = h[b];           jbot = t[b];           oaddr = b; }
        else if (r < 32)  { itop = h[b];           jbot = ns[b * 64 + r]; oaddr = B_DIM + b * 64 + r; }
        else              { itop = ns[b * 64 + r]; jbot = t[b];           oaddr = B_DIM + b * 64 + r; }
        sTop[tid] = itop; sBot[tid] = jbot; sOut[tid] = oaddr;
        b1s[tid] = b1[tid];
    }
    if (tid < 64) { b2s[tid] = b2[tid]; W3s[tid] = W3[tid]; }
    __syncthreads();

    // ---- phase 1: stage ALL of X1 (hi/lo, both chunks) and W2 (both chunks) ----
    {
        const int s1 = tid >> 1;            // sample
        const int kh = (tid & 1) * 32;      // k half within each 64-chunk
        const float* pt = g_Ptop + (size_t)sTop[s1] * H1_DIM;
        const float* pb = g_Pbot + (size_t)sBot[s1] * H1_DIM;
#pragma unroll
        for (int c = 0; c < 2; c++) {
            const int koff = c * 64;
#pragma unroll
            for (int g = 0; g < 8; g++) {
                int k = koff + kh + g * 4;
                float4 pa = *(const float4*)&pt[k];
                float4 pv = *(const float4*)&pb[k];
                float4 vb = *(const float4*)&b1s[k];
                float4 x;
                x.x = fmaxf(pa.x + pv.x + vb.x, 0.f);
                x.y = fmaxf(pa.y + pv.y + vb.y, 0.f);
                x.z = fmaxf(pa.z + pv.z + vb.z, 0.f);
                x.w = fmaxf(pa.w + pv.w + vb.w, 0.f);
                unsigned hi01, hi23, lo01, lo23;
                split4(x, hi01, hi23, lo01, lo23);
                unsigned off = (unsigned)(c * 16384) + SW128((unsigned)(s1 * 128 + (kh + g * 4) * 2));
                *(uint2*)(sm + M2_XHI + off) = make_uint2(hi01, hi23);
                *(uint2*)(sm + M2_XLO + off) = make_uint2(lo01, lo23);
            }
        }
        // W2 tiles: both chunks, hi+lo. 2048 uint2 groups over 256 threads.
#pragma unroll
        for (int it = 0; it < 8; it++) {
            int idx = it * 256 + tid;       // 0..2047
            int c = idx >> 10;              // chunk
            int rem = idx & 1023;
            int n = rem >> 4;
            int kq = rem & 15;
            unsigned off = (unsigned)(c * 8192) + SW128((unsigned)(n * 128 + kq * 8));
            *(uint2*)(sm + M2_WHI + off) = *(const uint2*)&g_W2thi[n * H1_DIM + c * 64 + kq * 4];
            *(uint2*)(sm + M2_WLO + off) = *(const uint2*)&g_W2tlo[n * H1_DIM + c * 64 + kq * 4];
        }
    }
    __syncthreads();

    // ---- phase 2: uninterrupted MMA (2 chunks x 4 k16 steps) ----
    const int wm = wid >> 1;        // 0..3 -> m0 = 32*wm
    const int wn = wid & 1;         // 0..1 -> nb = 32*wn
    const int nb = wn * 32;

    float acc[2][4][4];
#pragma unroll
    for (int i = 0; i < 2; i++)
#pragma unroll
        for (int j = 0; j < 4; j++)
#pragma unroll
            for (int q = 0; q < 4; q++) acc[i][j][q] = 0.f;

#pragma unroll
    for (int c = 0; c < 2; c++) {
        const unsigned xbhi = sb + M2_XHI + c * 16384;
        const unsigned xblo = sb + M2_XLO + c * 16384;
        const unsigned wbhi = sb + M2_WHI + c * 8192;
        const unsigned wblo = sb + M2_WLO + c * 8192;
#pragma unroll
        for (int ks = 0; ks < 4; ks++) {
            const int k0 = ks * 16;
            unsigned bh[4][2], bl[4][2], t0, t1, t2, t3;
            ldm_x4(bmat_addr(wbhi, nb,      k0, lane), t0, t1, t2, t3);
            bh[0][0] = t0; bh[0][1] = t1; bh[1][0] = t2; bh[1][1] = t3;
            ldm_x4(bmat_addr(wbhi, nb + 16, k0, lane), t0, t1, t2, t3);
            bh[2][0] = t0; bh[2][1] = t1; bh[3][0] = t2; bh[3][1] = t3;
            ldm_x4(bmat_addr(wblo, nb,      k0, lane), t0, t1, t2, t3);
            bl[0][0] = t0; bl[0][1] = t1; bl[1][0] = t2; bl[1][1] = t3;
            ldm_x4(bmat_addr(wblo, nb + 16, k0, lane), t0, t1, t2, t3);
            bl[2][0] = t0; bl[2][1] = t1; bl[3][0] = t2; bl[3][1] = t3;
#pragma unroll
            for (int mf = 0; mf < 2; mf++) {
                const int m0 = wm * 32 + mf * 16;
                unsigned ah0, ah1, ah2, ah3, al0, al1, al2, al3;
                ldm_x4(amat_addr(xbhi, m0, k0, lane), ah0, ah1, ah2, ah3);
                ldm_x4(amat_addr(xblo, m0, k0, lane), al0, al1, al2, al3);
#pragma unroll
                for (int nf = 0; nf < 4; nf++) {
                    mma_bf16(acc[mf][nf], ah0, ah1, ah2, ah3, bh[nf][0], bh[nf][1]);
                    mma_bf16(acc[mf][nf], ah0, ah1, ah2, ah3, bl[nf][0], bl[nf][1]);
                    mma_bf16(acc[mf][nf], al0, al1, al2, al3, bh[nf][0], bh[nf][1]);
                }
            }
        }
    }

    // ---- phase 3: relu(acc + b2) . W3, reduce ----
#pragma unroll
    for (int mf = 0; mf < 2; mf++) {
        float p0 = 0.f, p8 = 0.f;
#pragma unroll
        for (int nf = 0; nf < 4; nf++) {
            int n0 = nb + nf * 8 + 2 * (lane & 3);
            float b20 = b2s[n0], b21 = b2s[n0 + 1];
            float w30 = W3s[n0], w31 = W3s[n0 + 1];
            p0 = fmaf(fmaxf(acc[mf][nf][0] + b20, 0.f), w30, p0);
            p0 = fmaf(fmaxf(acc[mf][nf][1] + b21, 0.f), w31, p0);
            p8 = fmaf(fmaxf(acc[mf][nf][2] + b20, 0.f), w30, p8);
            p8 = fmaf(fmaxf(acc[mf][nf][3] + b21, 0.f), w31, p8);
        }
        p0 += __shfl_xor_sync(0xffffffffu, p0, 1);
        p0 += __shfl_xor_sync(0xffffffffu, p0, 2);
        p8 += __shfl_xor_sync(0xffffffffu, p8, 1);
        p8 += __shfl_xor_sync(0xffffffffu, p8, 2);
        if ((lane & 3) == 0) {
            int r = wm * 32 + mf * 16 + (lane >> 2);
            partial[r * 2 + wn]       = p0;
            partial[(r + 8) * 2 + wn] = p8;
        }
    }
    __syncthreads();
    if (tid < 128)
        out[sOut[tid]] = partial[tid * 2] + partial[tid * 2 + 1] + b3[0];
}

// ---------------------------------------------------------------------------
extern "C" void kernel_launch(void* const* d_in, const int* in_sizes, int n_in,
                              void* d_out, int out_size) {
    const float* embed = (const float*)d_in[0];
    const float* W1    = (const float*)d_in[1];
    const float* b1    = (const float*)d_in[2];
    const float* W2    = (const float*)d_in[3];
    const float* b2    = (const float*)d_in[4];
    const float* W3    = (const float*)d_in[5];
    const float* b3    = (const float*)d_in[6];
    const int*   h     = (const int*)d_in[7];
    const int*   t     = (const int*)d_in[8];
    const int*   ns    = (const int*)d_in[9];
    float* out = (float*)d_out;

    convert_w1_kernel<<<32, 256>>>(W1);
    convert_w2_kernel<<<32, 256>>>(W2);

    cudaFuncSetAttribute(gemm1_mma_kernel, cudaFuncAttributeMaxDynamicSharedMemorySize,
                         G1_SMEM);
    gemm1_mma_kernel<<<NBOT_TC + NTOP_TC, 256, G1_SMEM>>>(embed);

    cudaFuncSetAttribute(mlp2_mma_kernel, cudaFuncAttributeMaxDynamicSharedMemorySize,
                         M2_SMEM);
    mlp2_mma_kernel<<<(B_DIM * 65) / 128, 256, M2_SMEM>>>(h, t, ns, b1, b2, W3, b3, out);
}

// round 11
// speedup vs baseline: 1.5855x; 1.4308x over previous
#include <cuda_runtime.h>
#include <cuda_bf16.h>

#define D_DIM   512
#define H1_DIM  128
#define H2_DIM  64
#define B_DIM   2048
#define N_NODES 20000
#define N_DRUG  2000

typedef unsigned long long ull;

__device__ __forceinline__ unsigned smem_u32(const void* p) {
    unsigned a;
    asm("{ .reg .u64 t; cvta.to.shared.u64 t, %1; cvt.u32.u64 %0, t; }" : "=r"(a) : "l"(p));
    return a;
}

#define SW128(o) ((o) ^ ((((o) >> 3) & 0x70)))

// Scratch
__device__ float g_Ptop[N_DRUG  * H1_DIM];
__device__ float g_Pbot[N_NODES * H1_DIM];
__device__ __nv_bfloat16 g_Wthi[H1_DIM * 1024];    // W1^T hi [n][k]
__device__ __nv_bfloat16 g_Wtlo[H1_DIM * 1024];    // W1^T lo [n][k]
__device__ __nv_bfloat16 g_W2thi[H2_DIM * H1_DIM]; // W2^T hi [n][k]
__device__ __nv_bfloat16 g_W2tlo[H2_DIM * H1_DIM]; // W2^T lo [n][k]

// ---------------------------------------------------------------------------
// Kernel 0a: W1 -> bf16 hi/lo transposed, coalesced
// ---------------------------------------------------------------------------
__global__ void __launch_bounds__(256) convert_w1_kernel(const float* __restrict__ W1) {
    __shared__ unsigned short s_hi[128][34];
    __shared__ unsigned short s_lo[128][34];
    const int tid = threadIdx.x;
    const int k0 = blockIdx.x * 32;
#pragma unroll
    for (int it = 0; it < 16; it++) {
        int idx = it * 256 + tid;
        int kk = idx >> 7;
        int n  = idx & 127;
        float x = W1[(k0 + kk) * H1_DIM + n];
        __nv_bfloat16 hb = __float2bfloat16(x);
        float hf = __bfloat162float(hb);
        __nv_bfloat16 lb = __float2bfloat16(x - hf);
        s_hi[n][kk] = __bfloat16_as_ushort(hb);
        s_lo[n][kk] = __bfloat16_as_ushort(lb);
    }
    __syncthreads();
#pragma unroll
    for (int it = 0; it < 16; it++) {
        int idx = it * 256 + tid;
        int n  = idx >> 5;
        int kk = idx & 31;
        g_Wthi[n * 1024 + k0 + kk] = __ushort_as_bfloat16(s_hi[n][kk]);
        g_Wtlo[n * 1024 + k0 + kk] = __ushort_as_bfloat16(s_lo[n][kk]);
    }
}

// ---------------------------------------------------------------------------
// Kernel 0b: W2 -> bf16 hi/lo transposed (32 parallel blocks)
// ---------------------------------------------------------------------------
__global__ void __launch_bounds__(256) convert_w2_kernel(const float* __restrict__ W2) {
    int idx = blockIdx.x * 256 + threadIdx.x;
    int k = idx >> 6;
    int n = idx & 63;
    float x = W2[k * H2_DIM + n];
    __nv_bfloat16 hb = __float2bfloat16(x);
    float hf = __bfloat162float(hb);
    g_W2thi[n * H1_DIM + k] = hb;
    g_W2tlo[n * H1_DIM + k] = __float2bfloat16(x - hf);
}

// ---------------------------------------------------------------------------
// HMMA helpers (validated)
// ---------------------------------------------------------------------------
__device__ __forceinline__ void ldm_x4(unsigned addr, unsigned& r0, unsigned& r1,
                                       unsigned& r2, unsigned& r3) {
    asm volatile("ldmatrix.sync.aligned.m8n8.x4.shared.b16 {%0,%1,%2,%3}, [%4];"
                 : "=r"(r0), "=r"(r1), "=r"(r2), "=r"(r3) : "r"(addr));
}
__device__ __forceinline__ void mma_bf16(float* c, unsigned a0, unsigned a1,
                                         unsigned a2, unsigned a3,
                                         unsigned b0, unsigned b1) {
    asm volatile("mma.sync.aligned.m16n8k16.row.col.f32.bf16.bf16.f32 "
                 "{%0,%1,%2,%3}, {%4,%5,%6,%7}, {%8,%9}, {%0,%1,%2,%3};"
                 : "+f"(c[0]), "+f"(c[1]), "+f"(c[2]), "+f"(c[3])
                 : "r"(a0), "r"(a1), "r"(a2), "r"(a3), "r"(b0), "r"(b1));
}
__device__ __forceinline__ unsigned amat_addr(unsigned base, int m0, int k0, int lane) {
    unsigned off = (unsigned)((m0 + (lane & 15)) * 128 + ((k0 >> 3) + (lane >> 4)) * 16);
    return base + SW128(off);
}
__device__ __forceinline__ unsigned bmat_addr(unsigned base, int n0, int k0, int lane) {
    unsigned off = (unsigned)((n0 + (lane & 7) + ((lane >> 4) << 3)) * 128
                            + ((k0 >> 3) + ((lane >> 3) & 1)) * 16);
    return base + SW128(off);
}
__device__ __forceinline__ void split4(float4 v, unsigned& hi01, unsigned& hi23,
                                       unsigned& lo01, unsigned& lo23) {
    asm("cvt.rn.bf16x2.f32 %0, %1, %2;" : "=r"(hi01) : "f"(v.y), "f"(v.x));
    asm("cvt.rn.bf16x2.f32 %0, %1, %2;" : "=r"(hi23) : "f"(v.w), "f"(v.z));
    float h0 = __uint_as_float(hi01 << 16);
    float h1 = __uint_as_float(hi01 & 0xffff0000u);
    float h2 = __uint_as_float(hi23 << 16);
    float h3 = __uint_as_float(hi23 & 0xffff0000u);
    asm("cvt.rn.bf16x2.f32 %0, %1, %2;" : "=r"(lo01) : "f"(v.y - h1), "f"(v.x - h0));
    asm("cvt.rn.bf16x2.f32 %0, %1, %2;" : "=r"(lo23) : "f"(v.w - h3), "f"(v.z - h2));
}

// ---------------------------------------------------------------------------
// Kernel 1 v2: 64m x 64n tiles, 4 warps (warp = 16m x 64n), 690 blocks.
// Fixes per-SM tile quantization (173 x 12.3K-HMMA blocks -> 690 x 3K).
// smem: Ahi/Alo/Bhi/Blo 8KB each = 32KB (static).
// ---------------------------------------------------------------------------
#define G1_RT_BOT 313   // 64-row tiles over 20000
#define G1_RT_TOP 32    // over 2000
#define G1_GRID ((G1_RT_BOT + G1_RT_TOP) * 2)

__global__ void __launch_bounds__(128) gemm1_mma_kernel(const float* __restrict__ embed) {
    __shared__ char sm[32768];
    const unsigned sb = smem_u32(sm);
    const unsigned AHI = 0, ALO = 8192, BHI = 16384, BLO = 24576;
    const int tid = threadIdx.x;
    const int wid = tid >> 5;
    const int lane = tid & 31;

    int bx = blockIdx.x;
    const int nh = bx & 1;          // n-half: output cols [64*nh, 64*nh+64)
    int rt = bx >> 1;
    int woff, M, row0;
    float* P;
    if (rt < G1_RT_BOT) { woff = D_DIM; M = N_NODES; P = g_Pbot; row0 = rt * 64; }
    else { rt -= G1_RT_BOT; woff = 0; M = N_DRUG; P = g_Ptop; row0 = rt * 64; }
    const int rmax = M - 1;
    const int n0 = nh * 64;

    float acc[8][4];
#pragma unroll
    for (int i = 0; i < 8; i++)
#pragma unroll
        for (int q = 0; q < 4; q++) acc[i][q] = 0.f;

    for (int c = 0; c < 8; c++) {
        const int kb = c * 64;
        // ---- stage A: 64x64 fp32 -> bf16 hi/lo, coalesced (4-line warp LDGs) ----
#pragma unroll
        for (int g = 0; g < 8; g++) {
            int idx = g * 512 + tid * 4;        // float index in 64x64 tile
            int row = idx >> 6;                 // 0..63
            int col = idx & 63;
            int rg = min(row0 + row, rmax);
            float4 v = *(const float4*)&embed[(size_t)rg * D_DIM + kb + col];
            unsigned hi01, hi23, lo01, lo23;
            split4(v, hi01, hi23, lo01, lo23);
            unsigned off = SW128((unsigned)(row * 128 + col * 2));
            *(uint2*)(sm + AHI + off) = make_uint2(hi01, hi23);
            *(uint2*)(sm + ALO + off) = make_uint2(lo01, lo23);
        }
        // ---- stage B: 64 rows (n) x 64 k bf16 hi/lo, coalesced ----
#pragma unroll
        for (int g = 0; g < 8; g++) {
            int bidx = g * 128 + tid;           // uint2 index, 1024 total
            int row = bidx >> 4;                // 0..63
            int kc  = (bidx & 15) * 4;          // 0..60
            unsigned off = SW128((unsigned)(row * 128 + kc * 2));
            *(uint2*)(sm + BHI + off) =
                *(const uint2*)&g_Wthi[(n0 + row) * 1024 + woff + kb + kc];
            *(uint2*)(sm + BLO + off) =
                *(const uint2*)&g_Wtlo[(n0 + row) * 1024 + woff + kb + kc];
        }
        __syncthreads();

        // ---- compute: 4 k16 steps, warp tile 16m x 64n ----
        const int m0 = wid * 16;
#pragma unroll
        for (int ks = 0; ks < 4; ks++) {
            const int k0 = ks * 16;
            unsigned bh[8][2], bl[8][2], t0, t1, t2, t3;
#pragma unroll
            for (int seg = 0; seg < 4; seg++) {
                ldm_x4(bmat_addr(sb + BHI, seg * 16, k0, lane), t0, t1, t2, t3);
                bh[seg * 2][0] = t0; bh[seg * 2][1] = t1;
                bh[seg * 2 + 1][0] = t2; bh[seg * 2 + 1][1] = t3;
                ldm_x4(bmat_addr(sb + BLO, seg * 16, k0, lane), t0, t1, t2, t3);
                bl[seg * 2][0] = t0; bl[seg * 2][1] = t1;
                bl[seg * 2 + 1][0] = t2; bl[seg * 2 + 1][1] = t3;
            }
            unsigned ah0, ah1, ah2, ah3, al0, al1, al2, al3;
            ldm_x4(amat_addr(sb + AHI, m0, k0, lane), ah0, ah1, ah2, ah3);
            ldm_x4(amat_addr(sb + ALO, m0, k0, lane), al0, al1, al2, al3);
#pragma unroll
            for (int nf = 0; nf < 8; nf++) {
                mma_bf16(acc[nf], ah0, ah1, ah2, ah3, bh[nf][0], bh[nf][1]);
                mma_bf16(acc[nf], ah0, ah1, ah2, ah3, bl[nf][0], bl[nf][1]);
                mma_bf16(acc[nf], al0, al1, al2, al3, bh[nf][0], bh[nf][1]);
            }
        }
        __syncthreads();
    }

    // ---- epilogue ----
#pragma unroll
    for (int nf = 0; nf < 8; nf++) {
        int r = row0 + wid * 16 + (lane >> 2);
        int col = n0 + nf * 8 + 2 * (lane & 3);
        if (r < M)
            *(float2*)&P[(size_t)r * H1_DIM + col] = make_float2(acc[nf][0], acc[nf][1]);
        if (r + 8 < M)
            *(float2*)&P[(size_t)(r + 8) * H1_DIM + col] = make_float2(acc[nf][2], acc[nf][3]);
    }
}

// ---------------------------------------------------------------------------
// Kernel 2 v3: as R10 but WARP-PER-SAMPLE gather (4-line warp LDGs instead of
// 16-line -> 8x fewer L1tex wavefronts; gather now hides under MMA).
// ---------------------------------------------------------------------------
#define M2_XHI 0                  // 2 chunks x 16KB
#define M2_XLO 32768
#define M2_WHI 65536              // 2 chunks x 8KB
#define M2_WLO 81920
#define M2_MISC 98304
#define M2_SMEM (M2_MISC + (128 + 64 + 64 + 256 + 3 * 128) * 4)

__global__ void __launch_bounds__(256) mlp2_mma_kernel(
    const int* __restrict__ h, const int* __restrict__ t, const int* __restrict__ ns,
    const float* __restrict__ b1, const float* __restrict__ b2,
    const float* __restrict__ W3, const float* __restrict__ b3,
    float* __restrict__ out)
{
    extern __shared__ char sm[];
    const unsigned sb = smem_u32(sm);
    float* b1s   = (float*)(sm + M2_MISC);
    float* b2s   = b1s + 128;
    float* W3s   = b2s + 64;
    float* partial = W3s + 64;                 // [128][2]
    int* sTop = (int*)(partial + 256);
    int* sBot = sTop + 128;
    int* sOut = sBot + 128;

    const int tid = threadIdx.x;
    const int wid = tid >> 5;
    const int lane = tid & 31;

    // ---- phase 0: indices + small tensors ----
    if (tid < 128) {
        int S = blockIdx.x * 128 + tid;
        int b = S / 65;
        int r = S - b * 65;
        int itop, jbot, oaddr;
        if (r == 64)      { itop = h[b];           jbot = t[b];           oaddr = b; }
        else if (r < 32)  { itop = h[b];           jbot = ns[b * 64 + r]; oaddr = B_DIM + b * 64 + r; }
        else              { itop = ns[b * 64 + r]; jbot = t[b];           oaddr = B_DIM + b * 64 + r; }
        sTop[tid] = itop; sBot[tid] = jbot; sOut[tid] = oaddr;
        b1s[tid] = b1[tid];
    }
    if (tid < 64) { b2s[tid] = b2[tid]; W3s[tid] = W3[tid]; }
    __syncthreads();

    // ---- phase 1: gather + split, one warp per sample (coalesced) ----
    {
        const int kcol = lane * 4;              // 0..124
        const int cch = lane >> 4;              // chunk 0/1
        const int kin = (lane & 15) * 4;        // k within chunk
        const float4 vb = *(const float4*)&b1s[kcol];
#pragma unroll
        for (int it = 0; it < 16; it++) {
            int s = it * 8 + wid;
            const float* pt = g_Ptop + (size_t)sTop[s] * H1_DIM;
            const float* pb = g_Pbot + (size_t)sBot[s] * H1_DIM;
            float4 pa = *(const float4*)&pt[kcol];
            float4 pv = *(const float4*)&pb[kcol];
            float4 x;
            x.x = fmaxf(pa.x + pv.x + vb.x, 0.f);
            x.y = fmaxf(pa.y + pv.y + vb.y, 0.f);
            x.z = fmaxf(pa.z + pv.z + vb.z, 0.f);
            x.w = fmaxf(pa.w + pv.w + vb.w, 0.f);
            unsigned hi01, hi23, lo01, lo23;
            split4(x, hi01, hi23, lo01, lo23);
            unsigned off = (unsigned)(cch * 16384) + SW128((unsigned)(s * 128 + kin * 2));
            *(uint2*)(sm + M2_XHI + off) = make_uint2(hi01, hi23);
            *(uint2*)(sm + M2_XLO + off) = make_uint2(lo01, lo23);
        }
        // W2 tiles: both chunks, hi+lo (2048 uint2 over 256 threads)
#pragma unroll
        for (int it = 0; it < 8; it++) {
            int idx = it * 256 + tid;
            int c = idx >> 10;
            int rem = idx & 1023;
            int n = rem >> 4;
            int kq = rem & 15;
            unsigned off = (unsigned)(c * 8192) + SW128((unsigned)(n * 128 + kq * 8));
            *(uint2*)(sm + M2_WHI + off) = *(const uint2*)&g_W2thi[n * H1_DIM + c * 64 + kq * 4];
            *(uint2*)(sm + M2_WLO + off) = *(const uint2*)&g_W2tlo[n * H1_DIM + c * 64 + kq * 4];
        }
    }
    __syncthreads();

    // ---- phase 2: uninterrupted MMA ----
    const int wm = wid >> 1;
    const int wn = wid & 1;
    const int nb = wn * 32;

    float acc[2][4][4];
#pragma unroll
    for (int i = 0; i < 2; i++)
#pragma unroll
        for (int j = 0; j < 4; j++)
#pragma unroll
            for (int q = 0; q < 4; q++) acc[i][j][q] = 0.f;

#pragma unroll
    for (int c = 0; c < 2; c++) {
        const unsigned xbhi = sb + M2_XHI + c * 16384;
        const unsigned xblo = sb + M2_XLO + c * 16384;
        const unsigned wbhi = sb + M2_WHI + c * 8192;
        const unsigned wblo = sb + M2_WLO + c * 8192;
#pragma unroll
        for (int ks = 0; ks < 4; ks++) {
            const int k0 = ks * 16;
            unsigned bh[4][2], bl[4][2], t0, t1, t2, t3;
            ldm_x4(bmat_addr(wbhi, nb,      k0, lane), t0, t1, t2, t3);
            bh[0][0] = t0; bh[0][1] = t1; bh[1][0] = t2; bh[1][1] = t3;
            ldm_x4(bmat_addr(wbhi, nb + 16, k0, lane), t0, t1, t2, t3);
            bh[2][0] = t0; bh[2][1] = t1; bh[3][0] = t2; bh[3][1] = t3;
            ldm_x4(bmat_addr(wblo, nb,      k0, lane), t0, t1, t2, t3);
            bl[0][0] = t0; bl[0][1] = t1; bl[1][0] = t2; bl[1][1] = t3;
            ldm_x4(bmat_addr(wblo, nb + 16, k0, lane), t0, t1, t2, t3);
            bl[2][0] = t0; bl[2][1] = t1; bl[3][0] = t2; bl[3][1] = t3;
#pragma unroll
            for (int mf = 0; mf < 2; mf++) {
                const int m0 = wm * 32 + mf * 16;
                unsigned ah0, ah1, ah2, ah3, al0, al1, al2, al3;
                ldm_x4(amat_addr(xbhi, m0, k0, lane), ah0, ah1, ah2, ah3);
                ldm_x4(amat_addr(xblo, m0, k0, lane), al0, al1, al2, al3);
#pragma unroll
                for (int nf = 0; nf < 4; nf++) {
                    mma_bf16(acc[mf][nf], ah0, ah1, ah2, ah3, bh[nf][0], bh[nf][1]);
                    mma_bf16(acc[mf][nf], ah0, ah1, ah2, ah3, bl[nf][0], bl[nf][1]);
                    mma_bf16(acc[mf][nf], al0, al1, al2, al3, bh[nf][0], bh[nf][1]);
                }
            }
        }
    }

    // ---- phase 3: relu(acc + b2) . W3, reduce ----
#pragma unroll
    for (int mf = 0; mf < 2; mf++) {
        float p0 = 0.f, p8 = 0.f;
#pragma unroll
        for (int nf = 0; nf < 4; nf++) {
            int n0 = nb + nf * 8 + 2 * (lane & 3);
            float b20 = b2s[n0], b21 = b2s[n0 + 1];
            float w30 = W3s[n0], w31 = W3s[n0 + 1];
            p0 = fmaf(fmaxf(acc[mf][nf][0] + b20, 0.f), w30, p0);
            p0 = fmaf(fmaxf(acc[mf][nf][1] + b21, 0.f), w31, p0);
            p8 = fmaf(fmaxf(acc[mf][nf][2] + b20, 0.f), w30, p8);
            p8 = fmaf(fmaxf(acc[mf][nf][3] + b21, 0.f), w31, p8);
        }
        p0 += __shfl_xor_sync(0xffffffffu, p0, 1);
        p0 += __shfl_xor_sync(0xffffffffu, p0, 2);
        p8 += __shfl_xor_sync(0xffffffffu, p8, 1);
        p8 += __shfl_xor_sync(0xffffffffu, p8, 2);
        if ((lane & 3) == 0) {
            int r = wm * 32 + mf * 16 + (lane >> 2);
            partial[r * 2 + wn]       = p0;
            partial[(r + 8) * 2 + wn] = p8;
        }
    }
    __syncthreads();
    if (tid < 128)
        out[sOut[tid]] = partial[tid * 2] + partial[tid * 2 + 1] + b3[0];
}

// ---------------------------------------------------------------------------
extern "C" void kernel_launch(void* const* d_in, const int* in_sizes, int n_in,
                              void* d_out, int out_size) {
    const float* embed = (const float*)d_in[0];
    const float* W1    = (const float*)d_in[1];
    const float* b1    = (const float*)d_in[2];
    const float* W2    = (const float*)d_in[3];
    const float* b2    = (const float*)d_in[4];
    const float* W3    = (const float*)d_in[5];
    const float* b3    = (const float*)d_in[6];
    const int*   h     = (const int*)d_in[7];
    const int*   t     = (const int*)d_in[8];
    const int*   ns    = (const int*)d_in[9];
    float* out = (float*)d_out;

    convert_w1_kernel<<<32, 256>>>(W1);
    convert_w2_kernel<<<32, 256>>>(W2);

    gemm1_mma_kernel<<<G1_GRID, 128>>>(embed);

    cudaFuncSetAttribute(mlp2_mma_kernel, cudaFuncAttributeMaxDynamicSharedMemorySize,
                         M2_SMEM);
    mlp2_mma_kernel<<<(B_DIM * 65) / 128, 256, M2_SMEM>>>(h, t, ns, b1, b2, W3, b3, out);
}

// round 12
// speedup vs baseline: 1.9079x; 1.2033x over previous
#include <cuda_runtime.h>
#include <cuda_bf16.h>

#define D_DIM   512
#define H1_DIM  128
#define H2_DIM  64
#define B_DIM   2048
#define N_NODES 20000
#define N_DRUG  2000

typedef unsigned long long ull;

__device__ __forceinline__ unsigned smem_u32(const void* p) {
    unsigned a;
    asm("{ .reg .u64 t; cvta.to.shared.u64 t, %1; cvt.u32.u64 %0, t; }" : "=r"(a) : "l"(p));
    return a;
}

#define SW128(o) ((o) ^ ((((o) >> 3) & 0x70)))

// Scratch.  g_Pbot layout: rows [0,2000) = Pbot for node ids < 2000 (neg1);
//           rows [2000,4048) = P_t[b] = embed[t[b]] @ W1bot (pos/neg2, per-batch slot).
__device__ float g_Ptop[N_DRUG * H1_DIM];
__device__ float g_Pbot[4096 * H1_DIM];
__device__ __nv_bfloat16 g_Wthi[H1_DIM * 1024];    // W1^T hi [n][k]
__device__ __nv_bfloat16 g_Wtlo[H1_DIM * 1024];    // W1^T lo [n][k]
__device__ __nv_bfloat16 g_W2thi[H2_DIM * H1_DIM]; // W2^T hi [n][k]
__device__ __nv_bfloat16 g_W2tlo[H2_DIM * H1_DIM]; // W2^T lo [n][k]

// ---------------------------------------------------------------------------
// Kernel 0a: W1 -> bf16 hi/lo transposed, coalesced
// ---------------------------------------------------------------------------
__global__ void __launch_bounds__(256) convert_w1_kernel(const float* __restrict__ W1) {
    __shared__ unsigned short s_hi[128][34];
    __shared__ unsigned short s_lo[128][34];
    const int tid = threadIdx.x;
    const int k0 = blockIdx.x * 32;
#pragma unroll
    for (int it = 0; it < 16; it++) {
        int idx = it * 256 + tid;
        int kk = idx >> 7;
        int n  = idx & 127;
        float x = W1[(k0 + kk) * H1_DIM + n];
        __nv_bfloat16 hb = __float2bfloat16(x);
        float hf = __bfloat162float(hb);
        __nv_bfloat16 lb = __float2bfloat16(x - hf);
        s_hi[n][kk] = __bfloat16_as_ushort(hb);
        s_lo[n][kk] = __bfloat16_as_ushort(lb);
    }
    __syncthreads();
#pragma unroll
    for (int it = 0; it < 16; it++) {
        int idx = it * 256 + tid;
        int n  = idx >> 5;
        int kk = idx & 31;
        g_Wthi[n * 1024 + k0 + kk] = __ushort_as_bfloat16(s_hi[n][kk]);
        g_Wtlo[n * 1024 + k0 + kk] = __ushort_as_bfloat16(s_lo[n][kk]);
    }
}

// ---------------------------------------------------------------------------
// Kernel 0b: W2 -> bf16 hi/lo transposed (32 parallel blocks)
// ---------------------------------------------------------------------------
__global__ void __launch_bounds__(256) convert_w2_kernel(const float* __restrict__ W2) {
    int idx = blockIdx.x * 256 + threadIdx.x;
    int k = idx >> 6;
    int n = idx & 63;
    float x = W2[k * H2_DIM + n];
    __nv_bfloat16 hb = __float2bfloat16(x);
    float hf = __bfloat162float(hb);
    g_W2thi[n * H1_DIM + k] = hb;
    g_W2tlo[n * H1_DIM + k] = __float2bfloat16(x - hf);
}

// ---------------------------------------------------------------------------
// HMMA helpers (validated)
// ---------------------------------------------------------------------------
__device__ __forceinline__ void ldm_x4(unsigned addr, unsigned& r0, unsigned& r1,
                                       unsigned& r2, unsigned& r3) {
    asm volatile("ldmatrix.sync.aligned.m8n8.x4.shared.b16 {%0,%1,%2,%3}, [%4];"
                 : "=r"(r0), "=r"(r1), "=r"(r2), "=r"(r3) : "r"(addr));
}
__device__ __forceinline__ void mma_bf16(float* c, unsigned a0, unsigned a1,
                                         unsigned a2, unsigned a3,
                                         unsigned b0, unsigned b1) {
    asm volatile("mma.sync.aligned.m16n8k16.row.col.f32.bf16.bf16.f32 "
                 "{%0,%1,%2,%3}, {%4,%5,%6,%7}, {%8,%9}, {%0,%1,%2,%3};"
                 : "+f"(c[0]), "+f"(c[1]), "+f"(c[2]), "+f"(c[3])
                 : "r"(a0), "r"(a1), "r"(a2), "r"(a3), "r"(b0), "r"(b1));
}
__device__ __forceinline__ unsigned amat_addr(unsigned base, int m0, int k0, int lane) {
    unsigned off = (unsigned)((m0 + (lane & 15)) * 128 + ((k0 >> 3) + (lane >> 4)) * 16);
    return base + SW128(off);
}
__device__ __forceinline__ unsigned bmat_addr(unsigned base, int n0, int k0, int lane) {
    unsigned off = (unsigned)((n0 + (lane & 7) + ((lane >> 4) << 3)) * 128
                            + ((k0 >> 3) + ((lane >> 3) & 1)) * 16);
    return base + SW128(off);
}
__device__ __forceinline__ void split4(float4 v, unsigned& hi01, unsigned& hi23,
                                       unsigned& lo01, unsigned& lo23) {
    asm("cvt.rn.bf16x2.f32 %0, %1, %2;" : "=r"(hi01) : "f"(v.y), "f"(v.x));
    asm("cvt.rn.bf16x2.f32 %0, %1, %2;" : "=r"(hi23) : "f"(v.w), "f"(v.z));
    float h0 = __uint_as_float(hi01 << 16);
    float h1 = __uint_as_float(hi01 & 0xffff0000u);
    float h2 = __uint_as_float(hi23 << 16);
    float h3 = __uint_as_float(hi23 & 0xffff0000u);
    asm("cvt.rn.bf16x2.f32 %0, %1, %2;" : "=r"(lo01) : "f"(v.y - h1), "f"(v.x - h0));
    asm("cvt.rn.bf16x2.f32 %0, %1, %2;" : "=r"(lo23) : "f"(v.w - h3), "f"(v.z - h2));
}

// ---------------------------------------------------------------------------
// Kernel 1 v3: only the rows that are actually read.
//   bt  0..31 : Ptop rows [0,2000)   (dense, woff=0)
//   bt 32..63 : Pbot rows [0,2000)   (dense, woff=512)  -- neg1 targets
//   bt 64..95 : Pbot rows [2000,4048) = embed[t[b]] @ W1bot (gathered rows)
// 64m x 64n tiles, 4 warps, x2 n-halves -> 192 blocks.
// ---------------------------------------------------------------------------
#define G1_GRID 192

__global__ void __launch_bounds__(128) gemm1_mma_kernel(const float* __restrict__ embed,
                                                        const int* __restrict__ t) {
    __shared__ char sm[32768];
    __shared__ int t_s[64];
    const unsigned sb = smem_u32(sm);
    const unsigned AHI = 0, ALO = 8192, BHI = 16384, BLO = 24576;
    const int tid = threadIdx.x;
    const int wid = tid >> 5;
    const int lane = tid & 31;

    int bx = blockIdx.x;
    const int nh = bx & 1;
    int bt = bx >> 1;              // 0..95
    int woff, row0, M;
    float* P;
    bool gat = false;
    if (bt < 32)      { woff = 0;     P = g_Ptop; row0 = bt * 64;        M = N_DRUG; }
    else if (bt < 64) { woff = D_DIM; P = g_Pbot; row0 = (bt - 32) * 64; M = N_DRUG; }
    else { woff = D_DIM; P = g_Pbot + 2000 * H1_DIM; row0 = (bt - 64) * 64; M = B_DIM; gat = true; }
    const int n0 = nh * 64;

    if (gat && tid < 64) t_s[tid] = t[row0 + tid];
    __syncthreads();

    float acc[8][4];
#pragma unroll
    for (int i = 0; i < 8; i++)
#pragma unroll
        for (int q = 0; q < 4; q++) acc[i][q] = 0.f;

    for (int c = 0; c < 8; c++) {
        const int kb = c * 64;
        // ---- stage A: 64x64 fp32 -> bf16 hi/lo ----
#pragma unroll
        for (int g = 0; g < 8; g++) {
            int idx = g * 512 + tid * 4;
            int row = idx >> 6;
            int col = idx & 63;
            int rg = gat ? t_s[row] : min(row0 + row, N_DRUG - 1);
            float4 v = *(const float4*)&embed[(size_t)rg * D_DIM + kb + col];
            unsigned hi01, hi23, lo01, lo23;
            split4(v, hi01, hi23, lo01, lo23);
            unsigned off = SW128((unsigned)(row * 128 + col * 2));
            *(uint2*)(sm + AHI + off) = make_uint2(hi01, hi23);
            *(uint2*)(sm + ALO + off) = make_uint2(lo01, lo23);
        }
        // ---- stage B ----
#pragma unroll
        for (int g = 0; g < 8; g++) {
            int bidx = g * 128 + tid;
            int row = bidx >> 4;
            int kc  = (bidx & 15) * 4;
            unsigned off = SW128((unsigned)(row * 128 + kc * 2));
            *(uint2*)(sm + BHI + off) =
                *(const uint2*)&g_Wthi[(n0 + row) * 1024 + woff + kb + kc];
            *(uint2*)(sm + BLO + off) =
                *(const uint2*)&g_Wtlo[(n0 + row) * 1024 + woff + kb + kc];
        }
        __syncthreads();

        // ---- compute: term-major (RAW distance 8 between same-acc HMMAs) ----
        const int m0 = wid * 16;
#pragma unroll
        for (int ks = 0; ks < 4; ks++) {
            const int k0 = ks * 16;
            unsigned bh[8][2], bl[8][2], t0, t1, t2, t3;
#pragma unroll
            for (int seg = 0; seg < 4; seg++) {
                ldm_x4(bmat_addr(sb + BHI, seg * 16, k0, lane), t0, t1, t2, t3);
                bh[seg * 2][0] = t0; bh[seg * 2][1] = t1;
                bh[seg * 2 + 1][0] = t2; bh[seg * 2 + 1][1] = t3;
                ldm_x4(bmat_addr(sb + BLO, seg * 16, k0, lane), t0, t1, t2, t3);
                bl[seg * 2][0] = t0; bl[seg * 2][1] = t1;
                bl[seg * 2 + 1][0] = t2; bl[seg * 2 + 1][1] = t3;
            }
            unsigned ah0, ah1, ah2, ah3, al0, al1, al2, al3;
            ldm_x4(amat_addr(sb + AHI, m0, k0, lane), ah0, ah1, ah2, ah3);
            ldm_x4(amat_addr(sb + ALO, m0, k0, lane), al0, al1, al2, al3);
#pragma unroll
            for (int nf = 0; nf < 8; nf++)
                mma_bf16(acc[nf], ah0, ah1, ah2, ah3, bh[nf][0], bh[nf][1]);
#pragma unroll
            for (int nf = 0; nf < 8; nf++)
                mma_bf16(acc[nf], ah0, ah1, ah2, ah3, bl[nf][0], bl[nf][1]);
#pragma unroll
            for (int nf = 0; nf < 8; nf++)
                mma_bf16(acc[nf], al0, al1, al2, al3, bh[nf][0], bh[nf][1]);
        }
        __syncthreads();
    }

    // ---- epilogue ----
#pragma unroll
    for (int nf = 0; nf < 8; nf++) {
        int r = row0 + wid * 16 + (lane >> 2);
        int col = n0 + nf * 8 + 2 * (lane & 3);
        if (r < M)
            *(float2*)&P[(size_t)r * H1_DIM + col] = make_float2(acc[nf][0], acc[nf][1]);
        if (r + 8 < M)
            *(float2*)&P[(size_t)(r + 8) * H1_DIM + col] = make_float2(acc[nf][2], acc[nf][3]);
    }
}

// ---------------------------------------------------------------------------
// Kernel 2 v4: as R11 but bot index = 2000+b for pos/neg2 (P_t slots) and
// term-major HMMA ordering.
// ---------------------------------------------------------------------------
#define M2_XHI 0
#define M2_XLO 32768
#define M2_WHI 65536
#define M2_WLO 81920
#define M2_MISC 98304
#define M2_SMEM (M2_MISC + (128 + 64 + 64 + 256 + 3 * 128) * 4)

__global__ void __launch_bounds__(256) mlp2_mma_kernel(
    const int* __restrict__ h, const int* __restrict__ t, const int* __restrict__ ns,
    const float* __restrict__ b1, const float* __restrict__ b2,
    const float* __restrict__ W3, const float* __restrict__ b3,
    float* __restrict__ out)
{
    extern __shared__ char sm[];
    const unsigned sb = smem_u32(sm);
    float* b1s   = (float*)(sm + M2_MISC);
    float* b2s   = b1s + 128;
    float* W3s   = b2s + 64;
    float* partial = W3s + 64;
    int* sTop = (int*)(partial + 256);
    int* sBot = sTop + 128;
    int* sOut = sBot + 128;

    const int tid = threadIdx.x;
    const int wid = tid >> 5;
    const int lane = tid & 31;

    // ---- phase 0 ----
    if (tid < 128) {
        int S = blockIdx.x * 128 + tid;
        int b = S / 65;
        int r = S - b * 65;
        int itop, jbot, oaddr;
        if (r == 64)      { itop = h[b];           jbot = 2000 + b;       oaddr = b; }
        else if (r < 32)  { itop = h[b];           jbot = ns[b * 64 + r]; oaddr = B_DIM + b * 64 + r; }
        else              { itop = ns[b * 64 + r]; jbot = 2000 + b;       oaddr = B_DIM + b * 64 + r; }
        sTop[tid] = itop; sBot[tid] = jbot; sOut[tid] = oaddr;
        b1s[tid] = b1[tid];
    }
    if (tid < 64) { b2s[tid] = b2[tid]; W3s[tid] = W3[tid]; }
    __syncthreads();

    // ---- phase 1: gather + split, one warp per sample ----
    {
        const int kcol = lane * 4;
        const int cch = lane >> 4;
        const int kin = (lane & 15) * 4;
        const float4 vb = *(const float4*)&b1s[kcol];
#pragma unroll
        for (int it = 0; it < 16; it++) {
            int s = it * 8 + wid;
            const float* pt = g_Ptop + (size_t)sTop[s] * H1_DIM;
            const float* pb = g_Pbot + (size_t)sBot[s] * H1_DIM;
            float4 pa = *(const float4*)&pt[kcol];
            float4 pv = *(const float4*)&pb[kcol];
            float4 x;
            x.x = fmaxf(pa.x + pv.x + vb.x, 0.f);
            x.y = fmaxf(pa.y + pv.y + vb.y, 0.f);
            x.z = fmaxf(pa.z + pv.z + vb.z, 0.f);
            x.w = fmaxf(pa.w + pv.w + vb.w, 0.f);
            unsigned hi01, hi23, lo01, lo23;
            split4(x, hi01, hi23, lo01, lo23);
            unsigned off = (unsigned)(cch * 16384) + SW128((unsigned)(s * 128 + kin * 2));
            *(uint2*)(sm + M2_XHI + off) = make_uint2(hi01, hi23);
            *(uint2*)(sm + M2_XLO + off) = make_uint2(lo01, lo23);
        }
#pragma unroll
        for (int it = 0; it < 8; it++) {
            int idx = it * 256 + tid;
            int c = idx >> 10;
            int rem = idx & 1023;
            int n = rem >> 4;
            int kq = rem & 15;
            unsigned off = (unsigned)(c * 8192) + SW128((unsigned)(n * 128 + kq * 8));
            *(uint2*)(sm + M2_WHI + off) = *(const uint2*)&g_W2thi[n * H1_DIM + c * 64 + kq * 4];
            *(uint2*)(sm + M2_WLO + off) = *(const uint2*)&g_W2tlo[n * H1_DIM + c * 64 + kq * 4];
        }
    }
    __syncthreads();

    // ---- phase 2: MMA, term-major ordering ----
    const int wm = wid >> 1;
    const int wn = wid & 1;
    const int nb = wn * 32;

    float acc[2][4][4];
#pragma unroll
    for (int i = 0; i < 2; i++)
#pragma unroll
        for (int j = 0; j < 4; j++)
#pragma unroll
            for (int q = 0; q < 4; q++) acc[i][j][q] = 0.f;

#pragma unroll
    for (int c = 0; c < 2; c++) {
        const unsigned xbhi = sb + M2_XHI + c * 16384;
        const unsigned xblo = sb + M2_XLO + c * 16384;
        const unsigned wbhi = sb + M2_WHI + c * 8192;
        const unsigned wblo = sb + M2_WLO + c * 8192;
#pragma unroll
        for (int ks = 0; ks < 4; ks++) {
            const int k0 = ks * 16;
            unsigned bh[4][2], bl[4][2], t0, t1, t2, t3;
            ldm_x4(bmat_addr(wbhi, nb,      k0, lane), t0, t1, t2, t3);
            bh[0][0] = t0; bh[0][1] = t1; bh[1][0] = t2; bh[1][1] = t3;
            ldm_x4(bmat_addr(wbhi, nb + 16, k0, lane), t0, t1, t2, t3);
            bh[2][0] = t0; bh[2][1] = t1; bh[3][0] = t2; bh[3][1] = t3;
            ldm_x4(bmat_addr(wblo, nb,      k0, lane), t0, t1, t2, t3);
            bl[0][0] = t0; bl[0][1] = t1; bl[1][0] = t2; bl[1][1] = t3;
            ldm_x4(bmat_addr(wblo, nb + 16, k0, lane), t0, t1, t2, t3);
            bl[2][0] = t0; bl[2][1] = t1; bl[3][0] = t2; bl[3][1] = t3;

            unsigned ah[2][4], al[2][4];
#pragma unroll
            for (int mf = 0; mf < 2; mf++) {
                const int m0 = wm * 32 + mf * 16;
                ldm_x4(amat_addr(xbhi, m0, k0, lane), ah[mf][0], ah[mf][1], ah[mf][2], ah[mf][3]);
                ldm_x4(amat_addr(xblo, m0, k0, lane), al[mf][0], al[mf][1], al[mf][2], al[mf][3]);
            }
#pragma unroll
            for (int mf = 0; mf < 2; mf++)
#pragma unroll
                for (int nf = 0; nf < 4; nf++)
                    mma_bf16(acc[mf][nf], ah[mf][0], ah[mf][1], ah[mf][2], ah[mf][3],
                             bh[nf][0], bh[nf][1]);
#pragma unroll
            for (int mf = 0; mf < 2; mf++)
#pragma unroll
                for (int nf = 0; nf < 4; nf++)
                    mma_bf16(acc[mf][nf], ah[mf][0], ah[mf][1], ah[mf][2], ah[mf][3],
                             bl[nf][0], bl[nf][1]);
#pragma unroll
            for (int mf = 0; mf < 2; mf++)
#pragma unroll
                for (int nf = 0; nf < 4; nf++)
                    mma_bf16(acc[mf][nf], al[mf][0], al[mf][1], al[mf][2], al[mf][3],
                             bh[nf][0], bh[nf][1]);
        }
    }

    // ---- phase 3 ----
#pragma unroll
    for (int mf = 0; mf < 2; mf++) {
        float p0 = 0.f, p8 = 0.f;
#pragma unroll
        for (int nf = 0; nf < 4; nf++) {
            int n0 = nb + nf * 8 + 2 * (lane & 3);
            float b20 = b2s[n0], b21 = b2s[n0 + 1];
            float w30 = W3s[n0], w31 = W3s[n0 + 1];
            p0 = fmaf(fmaxf(acc[mf][nf][0] + b20, 0.f), w30, p0);
            p0 = fmaf(fmaxf(acc[mf][nf][1] + b21, 0.f), w31, p0);
            p8 = fmaf(fmaxf(acc[mf][nf][2] + b20, 0.f), w30, p8);
            p8 = fmaf(fmaxf(acc[mf][nf][3] + b21, 0.f), w31, p8);
        }
        p0 += __shfl_xor_sync(0xffffffffu, p0, 1);
        p0 += __shfl_xor_sync(0xffffffffu, p0, 2);
        p8 += __shfl_xor_sync(0xffffffffu, p8, 1);
        p8 += __shfl_xor_sync(0xffffffffu, p8, 2);
        if ((lane & 3) == 0) {
            int r = wm * 32 + mf * 16 + (lane >> 2);
            partial[r * 2 + wn]       = p0;
            partial[(r + 8) * 2 + wn] = p8;
        }
    }
    __syncthreads();
    if (tid < 128)
        out[sOut[tid]] = partial[tid * 2] + partial[tid * 2 + 1] + b3[0];
}

// ---------------------------------------------------------------------------
extern "C" void kernel_launch(void* const* d_in, const int* in_sizes, int n_in,
                              void* d_out, int out_size) {
    const float* embed = (const float*)d_in[0];
    const float* W1    = (const float*)d_in[1];
    const float* b1    = (const float*)d_in[2];
    const float* W2    = (const float*)d_in[3];
    const float* b2    = (const float*)d_in[4];
    const float* W3    = (const float*)d_in[5];
    const float* b3    = (const float*)d_in[6];
    const int*   h     = (const int*)d_in[7];
    const int*   t     = (const int*)d_in[8];
    const int*   ns    = (const int*)d_in[9];
    float* out = (float*)d_out;

    convert_w1_kernel<<<32, 256>>>(W1);
    convert_w2_kernel<<<32, 256>>>(W2);

    gemm1_mma_kernel<<<G1_GRID, 128>>>(embed, t);

    cudaFuncSetAttribute(mlp2_mma_kernel, cudaFuncAttributeMaxDynamicSharedMemorySize,
                         M2_SMEM);
    mlp2_mma_kernel<<<(B_DIM * 65) / 128, 256, M2_SMEM>>>(h, t, ns, b1, b2, W3, b3, out);
}

// round 13
// speedup vs baseline: 1.9724x; 1.0338x over previous
#include <cuda_runtime.h>
#include <cuda_bf16.h>

#define D_DIM   512
#define H1_DIM  128
#define H2_DIM  64
#define B_DIM   2048
#define N_NODES 20000
#define N_DRUG  2000

typedef unsigned long long ull;

__device__ __forceinline__ unsigned smem_u32(const void* p) {
    unsigned a;
    asm("{ .reg .u64 t; cvta.to.shared.u64 t, %1; cvt.u32.u64 %0, t; }" : "=r"(a) : "l"(p));
    return a;
}

#define SW128(o) ((o) ^ ((((o) >> 3) & 0x70)))
#define BAR_SYNC(id, n)   asm volatile("bar.sync %0, %1;"   :: "r"(id), "r"(n) : "memory")
#define BAR_ARRIVE(id, n) asm volatile("bar.arrive %0, %1;" :: "r"(id), "r"(n) : "memory")

// Scratch.  g_Pbot rows [0,2000) = dense Pbot (neg1); rows [2000,4048) = P_t[b].
__device__ float g_Ptop[N_DRUG * H1_DIM];
__device__ float g_Pbot[4096 * H1_DIM];
__device__ __nv_bfloat16 g_Wthi[H1_DIM * 1024];
__device__ __nv_bfloat16 g_Wtlo[H1_DIM * 1024];
__device__ __nv_bfloat16 g_W2thi[H2_DIM * H1_DIM];
__device__ __nv_bfloat16 g_W2tlo[H2_DIM * H1_DIM];

// ---------------------------------------------------------------------------
// Kernel 0a/0b: weight conversion (validated)
// ---------------------------------------------------------------------------
__global__ void __launch_bounds__(256) convert_w1_kernel(const float* __restrict__ W1) {
    __shared__ unsigned short s_hi[128][34];
    __shared__ unsigned short s_lo[128][34];
    const int tid = threadIdx.x;
    const int k0 = blockIdx.x * 32;
#pragma unroll
    for (int it = 0; it < 16; it++) {
        int idx = it * 256 + tid;
        int kk = idx >> 7;
        int n  = idx & 127;
        float x = W1[(k0 + kk) * H1_DIM + n];
        __nv_bfloat16 hb = __float2bfloat16(x);
        float hf = __bfloat162float(hb);
        __nv_bfloat16 lb = __float2bfloat16(x - hf);
        s_hi[n][kk] = __bfloat16_as_ushort(hb);
        s_lo[n][kk] = __bfloat16_as_ushort(lb);
    }
    __syncthreads();
#pragma unroll
    for (int it = 0; it < 16; it++) {
        int idx = it * 256 + tid;
        int n  = idx >> 5;
        int kk = idx & 31;
        g_Wthi[n * 1024 + k0 + kk] = __ushort_as_bfloat16(s_hi[n][kk]);
        g_Wtlo[n * 1024 + k0 + kk] = __ushort_as_bfloat16(s_lo[n][kk]);
    }
}

__global__ void __launch_bounds__(256) convert_w2_kernel(const float* __restrict__ W2) {
    int idx = blockIdx.x * 256 + threadIdx.x;
    int k = idx >> 6;
    int n = idx & 63;
    float x = W2[k * H2_DIM + n];
    __nv_bfloat16 hb = __float2bfloat16(x);
    float hf = __bfloat162float(hb);
    g_W2thi[n * H1_DIM + k] = hb;
    g_W2tlo[n * H1_DIM + k] = __float2bfloat16(x - hf);
}

// ---------------------------------------------------------------------------
// HMMA helpers (validated)
// ---------------------------------------------------------------------------
__device__ __forceinline__ void ldm_x4(unsigned addr, unsigned& r0, unsigned& r1,
                                       unsigned& r2, unsigned& r3) {
    asm volatile("ldmatrix.sync.aligned.m8n8.x4.shared.b16 {%0,%1,%2,%3}, [%4];"
                 : "=r"(r0), "=r"(r1), "=r"(r2), "=r"(r3) : "r"(addr));
}
__device__ __forceinline__ void mma_bf16(float* c, unsigned a0, unsigned a1,
                                         unsigned a2, unsigned a3,
                                         unsigned b0, unsigned b1) {
    asm volatile("mma.sync.aligned.m16n8k16.row.col.f32.bf16.bf16.f32 "
                 "{%0,%1,%2,%3}, {%4,%5,%6,%7}, {%8,%9}, {%0,%1,%2,%3};"
                 : "+f"(c[0]), "+f"(c[1]), "+f"(c[2]), "+f"(c[3])
                 : "r"(a0), "r"(a1), "r"(a2), "r"(a3), "r"(b0), "r"(b1));
}
__device__ __forceinline__ unsigned amat_addr(unsigned base, int m0, int k0, int lane) {
    unsigned off = (unsigned)((m0 + (lane & 15)) * 128 + ((k0 >> 3) + (lane >> 4)) * 16);
    return base + SW128(off);
}
__device__ __forceinline__ unsigned bmat_addr(unsigned base, int n0, int k0, int lane) {
    unsigned off = (unsigned)((n0 + (lane & 7) + ((lane >> 4) << 3)) * 128
                            + ((k0 >> 3) + ((lane >> 3) & 1)) * 16);
    return base + SW128(off);
}
__device__ __forceinline__ void split4(float4 v, unsigned& hi01, unsigned& hi23,
                                       unsigned& lo01, unsigned& lo23) {
    asm("cvt.rn.bf16x2.f32 %0, %1, %2;" : "=r"(hi01) : "f"(v.y), "f"(v.x));
    asm("cvt.rn.bf16x2.f32 %0, %1, %2;" : "=r"(hi23) : "f"(v.w), "f"(v.z));
    float h0 = __uint_as_float(hi01 << 16);
    float h1 = __uint_as_float(hi01 & 0xffff0000u);
    float h2 = __uint_as_float(hi23 << 16);
    float h3 = __uint_as_float(hi23 & 0xffff0000u);
    asm("cvt.rn.bf16x2.f32 %0, %1, %2;" : "=r"(lo01) : "f"(v.y - h1), "f"(v.x - h0));
    asm("cvt.rn.bf16x2.f32 %0, %1, %2;" : "=r"(lo23) : "f"(v.w - h3), "f"(v.z - h2));
}

// ---------------------------------------------------------------------------
// Kernel 1 v4: same row set as R12, now 256 threads (8 warps, 16m x 32n each)
// so staging is spread over 2x threads and 8 warps hide LDG latency.
// ---------------------------------------------------------------------------
#define G1_GRID 192

__global__ void __launch_bounds__(256) gemm1_mma_kernel(const float* __restrict__ embed,
                                                        const int* __restrict__ t) {
    __shared__ char sm[32768];
    __shared__ int t_s[64];
    const unsigned sb = smem_u32(sm);
    const unsigned AHI = 0, ALO = 8192, BHI = 16384, BLO = 24576;
    const int tid = threadIdx.x;
    const int wid = tid >> 5;
    const int lane = tid & 31;

    int bx = blockIdx.x;
    const int nh = bx & 1;
    int bt = bx >> 1;
    int woff, row0, M;
    float* P;
    bool gat = false;
    if (bt < 32)      { woff = 0;     P = g_Ptop; row0 = bt * 64;        M = N_DRUG; }
    else if (bt < 64) { woff = D_DIM; P = g_Pbot; row0 = (bt - 32) * 64; M = N_DRUG; }
    else { woff = D_DIM; P = g_Pbot + 2000 * H1_DIM; row0 = (bt - 64) * 64; M = B_DIM; gat = true; }
    const int n0 = nh * 64;

    if (gat && tid < 64) t_s[tid] = t[row0 + tid];
    __syncthreads();

    const int wr = wid >> 1;        // 0..3 -> m0 = 16*wr
    const int wc = wid & 1;         // 0..1 -> nbw = 32*wc
    const int m0 = wr * 16;
    const int nbw = wc * 32;

    float acc[4][4];
#pragma unroll
    for (int i = 0; i < 4; i++)
#pragma unroll
        for (int q = 0; q < 4; q++) acc[i][q] = 0.f;

    for (int c = 0; c < 8; c++) {
        const int kb = c * 64;
        // ---- stage A (4 iters/thread) ----
#pragma unroll
        for (int g = 0; g < 4; g++) {
            int idx = g * 1024 + tid * 4;
            int row = idx >> 6;
            int col = idx & 63;
            int rg = gat ? t_s[row] : min(row0 + row, N_DRUG - 1);
            float4 v = *(const float4*)&embed[(size_t)rg * D_DIM + kb + col];
            unsigned hi01, hi23, lo01, lo23;
            split4(v, hi01, hi23, lo01, lo23);
            unsigned off = SW128((unsigned)(row * 128 + col * 2));
            *(uint2*)(sm + AHI + off) = make_uint2(hi01, hi23);
            *(uint2*)(sm + ALO + off) = make_uint2(lo01, lo23);
        }
        // ---- stage B (4 iters/thread) ----
#pragma unroll
        for (int g = 0; g < 4; g++) {
            int bidx = g * 256 + tid;
            int row = bidx >> 4;
            int kc  = (bidx & 15) * 4;
            unsigned off = SW128((unsigned)(row * 128 + kc * 2));
            *(uint2*)(sm + BHI + off) =
                *(const uint2*)&g_Wthi[(n0 + row) * 1024 + woff + kb + kc];
            *(uint2*)(sm + BLO + off) =
                *(const uint2*)&g_Wtlo[(n0 + row) * 1024 + woff + kb + kc];
        }
        __syncthreads();

        // ---- compute ----
#pragma unroll
        for (int ks = 0; ks < 4; ks++) {
            const int k0 = ks * 16;
            unsigned bh[4][2], bl[4][2], t0, t1, t2, t3;
            ldm_x4(bmat_addr(sb + BHI, nbw,      k0, lane), t0, t1, t2, t3);
            bh[0][0] = t0; bh[0][1] = t1; bh[1][0] = t2; bh[1][1] = t3;
            ldm_x4(bmat_addr(sb + BHI, nbw + 16, k0, lane), t0, t1, t2, t3);
            bh[2][0] = t0; bh[2][1] = t1; bh[3][0] = t2; bh[3][1] = t3;
            ldm_x4(bmat_addr(sb + BLO, nbw,      k0, lane), t0, t1, t2, t3);
            bl[0][0] = t0; bl[0][1] = t1; bl[1][0] = t2; bl[1][1] = t3;
            ldm_x4(bmat_addr(sb + BLO, nbw + 16, k0, lane), t0, t1, t2, t3);
            bl[2][0] = t0; bl[2][1] = t1; bl[3][0] = t2; bl[3][1] = t3;
            unsigned ah0, ah1, ah2, ah3, al0, al1, al2, al3;
            ldm_x4(amat_addr(sb + AHI, m0, k0, lane), ah0, ah1, ah2, ah3);
            ldm_x4(amat_addr(sb + ALO, m0, k0, lane), al0, al1, al2, al3);
#pragma unroll
            for (int nf = 0; nf < 4; nf++)
                mma_bf16(acc[nf], ah0, ah1, ah2, ah3, bh[nf][0], bh[nf][1]);
#pragma unroll
            for (int nf = 0; nf < 4; nf++)
                mma_bf16(acc[nf], ah0, ah1, ah2, ah3, bl[nf][0], bl[nf][1]);
#pragma unroll
            for (int nf = 0; nf < 4; nf++)
                mma_bf16(acc[nf], al0, al1, al2, al3, bh[nf][0], bh[nf][1]);
        }
        __syncthreads();
    }

    // ---- epilogue ----
#pragma unroll
    for (int nf = 0; nf < 4; nf++) {
        int r = row0 + m0 + (lane >> 2);
        int col = n0 + nbw + nf * 8 + 2 * (lane & 3);
        if (r < M)
            *(float2*)&P[(size_t)r * H1_DIM + col] = make_float2(acc[nf][0], acc[nf][1]);
        if (r + 8 < M)
            *(float2*)&P[(size_t)(r + 8) * H1_DIM + col] = make_float2(acc[nf][2], acc[nf][3]);
    }
}

// ---------------------------------------------------------------------------
// Kernel 2 v5: warp-specialized producer/consumer.
//   128 samples/block in 4 groups of 32; warps 4-7 gather, warps 0-3 MMA.
//   Ping-pong over 2 X buffers via named barriers:
//     FULL[buf] = id 1+buf (count 256), FREE[buf] = id 3+buf (count 256).
//   smem: X 32KB + W2 32KB + misc -> ~69KB -> 3 blocks/SM.
// ---------------------------------------------------------------------------
#define M2_XHI 0                      // 2 bufs x 8KB (each: 2 chunks x 4KB)
#define M2_XLO 16384
#define M2_WHI 32768                  // 2 chunks x 8KB
#define M2_WLO 49152
#define M2_MISC 65536
// misc: b1s[128], b2s[64], W3s[64], partial[256] floats + sTop/sBot/sOut[128] ints
#define M2_SMEM (M2_MISC + (128 + 64 + 64 + 256) * 4 + 3 * 128 * 4)

__global__ void __launch_bounds__(256, 3) mlp2_mma_kernel(
    const int* __restrict__ h, const int* __restrict__ t, const int* __restrict__ ns,
    const float* __restrict__ b1, const float* __restrict__ b2,
    const float* __restrict__ W3, const float* __restrict__ b3,
    float* __restrict__ out)
{
    extern __shared__ char sm[];
    const unsigned sb = smem_u32(sm);
    float* b1s     = (float*)(sm + M2_MISC);
    float* b2s     = b1s + 128;
    float* W3s     = b2s + 64;
    float* partial = W3s + 64;                 // [4 groups][32 rows][2 halves]
    int* sTop = (int*)(partial + 256);
    int* sBot = sTop + 128;
    int* sOut = sBot + 128;

    const int tid = threadIdx.x;
    const int wid = tid >> 5;
    const int lane = tid & 31;

    // ---- phase 0: indices + small tensors + W2 tiles (all 256 threads) ----
    if (tid < 128) {
        int S = blockIdx.x * 128 + tid;
        int b = S / 65;
        int r = S - b * 65;
        int itop, jbot, oaddr;
        if (r == 64)      { itop = h[b];           jbot = 2000 + b;       oaddr = b; }
        else if (r < 32)  { itop = h[b];           jbot = ns[b * 64 + r]; oaddr = B_DIM + b * 64 + r; }
        else              { itop = ns[b * 64 + r]; jbot = 2000 + b;       oaddr = B_DIM + b * 64 + r; }
        sTop[tid] = itop; sBot[tid] = jbot; sOut[tid] = oaddr;
        b1s[tid] = b1[tid];
    }
    if (tid < 64) { b2s[tid] = b2[tid]; W3s[tid] = W3[tid]; }
#pragma unroll
    for (int it = 0; it < 8; it++) {
        int idx = it * 256 + tid;       // 2048 uint2 groups
        int c = idx >> 10;
        int rem = idx & 1023;
        int n = rem >> 4;
        int kq = rem & 15;
        unsigned off = (unsigned)(c * 8192) + SW128((unsigned)(n * 128 + kq * 8));
        *(uint2*)(sm + M2_WHI + off) = *(const uint2*)&g_W2thi[n * H1_DIM + c * 64 + kq * 4];
        *(uint2*)(sm + M2_WLO + off) = *(const uint2*)&g_W2tlo[n * H1_DIM + c * 64 + kq * 4];
    }
    __syncthreads();

    if (wid >= 4) {
        // ================= PRODUCER (warps 4-7) =================
        const int pw = wid - 4;
        const int kcol = lane * 4;          // 0..124
        const int cch = lane >> 4;          // chunk 0/1
        const int kin = (lane & 15) * 4;    // k within chunk
        const float4 vb = *(const float4*)&b1s[kcol];
#pragma unroll
        for (int g = 0; g < 4; g++) {
            const int buf = g & 1;
            if (g >= 2) BAR_SYNC(3 + buf, 256);
#pragma unroll
            for (int it = 0; it < 8; it++) {
                int sl = pw * 8 + it;           // row in group, 0..31
                int s = g * 32 + sl;
                const float* pt = g_Ptop + (size_t)sTop[s] * H1_DIM;
                const float* pb = g_Pbot + (size_t)sBot[s] * H1_DIM;
                float4 pa = *(const float4*)&pt[kcol];
                float4 pv = *(const float4*)&pb[kcol];
                float4 x;
                x.x = fmaxf(pa.x + pv.x + vb.x, 0.f);
                x.y = fmaxf(pa.y + pv.y + vb.y, 0.f);
                x.z = fmaxf(pa.z + pv.z + vb.z, 0.f);
                x.w = fmaxf(pa.w + pv.w + vb.w, 0.f);
                unsigned hi01, hi23, lo01, lo23;
                split4(x, hi01, hi23, lo01, lo23);
                unsigned off = (unsigned)(buf * 8192 + cch * 4096)
                             + SW128((unsigned)(sl * 128 + kin * 2));
                *(uint2*)(sm + M2_XHI + off) = make_uint2(hi01, hi23);
                *(uint2*)(sm + M2_XLO + off) = make_uint2(lo01, lo23);
            }
            BAR_ARRIVE(1 + buf, 256);
        }
    } else {
        // ================= CONSUMER (warps 0-3) =================
        const int half = wid >> 1;          // n half
        const int m0 = (wid & 1) * 16;      // row base within group
        const int nb = half * 32;
#pragma unroll
        for (int g = 0; g < 4; g++) {
            const int buf = g & 1;
            BAR_SYNC(1 + buf, 256);

            float acc[4][4];
#pragma unroll
            for (int j = 0; j < 4; j++)
#pragma unroll
                for (int q = 0; q < 4; q++) acc[j][q] = 0.f;

#pragma unroll
            for (int c = 0; c < 2; c++) {
                const unsigned xbhi = sb + M2_XHI + buf * 8192 + c * 4096;
                const unsigned xblo = sb + M2_XLO + buf * 8192 + c * 4096;
                const unsigned wbhi = sb + M2_WHI + c * 8192;
                const unsigned wblo = sb + M2_WLO + c * 8192;
#pragma unroll
                for (int ks = 0; ks < 4; ks++) {
                    const int k0 = ks * 16;
                    unsigned bh[4][2], bl[4][2], t0, t1, t2, t3;
                    ldm_x4(bmat_addr(wbhi, nb,      k0, lane), t0, t1, t2, t3);
                    bh[0][0] = t0; bh[0][1] = t1; bh[1][0] = t2; bh[1][1] = t3;
                    ldm_x4(bmat_addr(wbhi, nb + 16, k0, lane), t0, t1, t2, t3);
                    bh[2][0] = t0; bh[2][1] = t1; bh[3][0] = t2; bh[3][1] = t3;
                    ldm_x4(bmat_addr(wblo, nb,      k0, lane), t0, t1, t2, t3);
                    bl[0][0] = t0; bl[0][1] = t1; bl[1][0] = t2; bl[1][1] = t3;
                    ldm_x4(bmat_addr(wblo, nb + 16, k0, lane), t0, t1, t2, t3);
                    bl[2][0] = t0; bl[2][1] = t1; bl[3][0] = t2; bl[3][1] = t3;
                    unsigned ah0, ah1, ah2, ah3, al0, al1, al2, al3;
                    ldm_x4(amat_addr(xbhi, m0, k0, lane), ah0, ah1, ah2, ah3);
                    ldm_x4(amat_addr(xblo, m0, k0, lane), al0, al1, al2, al3);
#pragma unroll
                    for (int nf = 0; nf < 4; nf++)
                        mma_bf16(acc[nf], ah0, ah1, ah2, ah3, bh[nf][0], bh[nf][1]);
#pragma unroll
                    for (int nf = 0; nf < 4; nf++)
                        mma_bf16(acc[nf], ah0, ah1, ah2, ah3, bl[nf][0], bl[nf][1]);
#pragma unroll
                    for (int nf = 0; nf < 4; nf++)
                        mma_bf16(acc[nf], al0, al1, al2, al3, bh[nf][0], bh[nf][1]);
                }
            }
            BAR_ARRIVE(3 + buf, 256);   // release buffer before layer-3 math

            // layer 3 partials for this group
            float p0 = 0.f, p8 = 0.f;
#pragma unroll
            for (int nf = 0; nf < 4; nf++) {
                int n0i = nb + nf * 8 + 2 * (lane & 3);
                float b20 = b2s[n0i], b21 = b2s[n0i + 1];
                float w30 = W3s[n0i], w31 = W3s[n0i + 1];
                p0 = fmaf(fmaxf(acc[nf][0] + b20, 0.f), w30, p0);
                p0 = fmaf(fmaxf(acc[nf][1] + b21, 0.f), w31, p0);
                p8 = fmaf(fmaxf(acc[nf][2] + b20, 0.f), w30, p8);
                p8 = fmaf(fmaxf(acc[nf][3] + b21, 0.f), w31, p8);
            }
            p0 += __shfl_xor_sync(0xffffffffu, p0, 1);
            p0 += __shfl_xor_sync(0xffffffffu, p0, 2);
            p8 += __shfl_xor_sync(0xffffffffu, p8, 1);
            p8 += __shfl_xor_sync(0xffffffffu, p8, 2);
            if ((lane & 3) == 0) {
                int r = m0 + (lane >> 2);
                partial[g * 64 + r * 2 + half]       = p0;
                partial[g * 64 + (r + 8) * 2 + half] = p8;
            }
        }
        BAR_SYNC(5, 128);               // consumers only
        if (tid < 128) {
            int g = tid >> 5, r = tid & 31;
            out[sOut[tid]] = partial[g * 64 + r * 2] + partial[g * 64 + r * 2 + 1] + b3[0];
        }
    }
}

// ---------------------------------------------------------------------------
extern "C" void kernel_launch(void* const* d_in, const int* in_sizes, int n_in,
                              void* d_out, int out_size) {
    const float* embed = (const float*)d_in[0];
    const float* W1    = (const float*)d_in[1];
    const float* b1    = (const float*)d_in[2];
    const float* W2    = (const float*)d_in[3];
    const float* b2    = (const float*)d_in[4];
    const float* W3    = (const float*)d_in[5];
    const float* b3    = (const float*)d_in[6];
    const int*   h     = (const int*)d_in[7];
    const int*   t     = (const int*)d_in[8];
    const int*   ns    = (const int*)d_in[9];
    float* out = (float*)d_out;

    convert_w1_kernel<<<32, 256>>>(W1);
    convert_w2_kernel<<<32, 256>>>(W2);

    gemm1_mma_kernel<<<G1_GRID, 256>>>(embed, t);

    cudaFuncSetAttribute(mlp2_mma_kernel, cudaFuncAttributeMaxDynamicSharedMemorySize,
                         M2_SMEM);
    mlp2_mma_kernel<<<(B_DIM * 65) / 128, 256, M2_SMEM>>>(h, t, ns, b1, b2, W3, b3, out);
}